// round 8
// baseline (speedup 1.0000x reference)
#include <cuda_runtime.h>
#include <cstdint>
#include <cstddef>

// ---------------------------------------------------------------------------
// Problem constants
// ---------------------------------------------------------------------------
namespace {
constexpr int N_   = 50000;
constexpr int D_   = 160;     // = H*C
constexpr int H_   = 5;
constexpr int E_   = 800000;
constexpr int ED_  = 16;
constexpr int HID_ = 512;
constexpr float EPS_   = 1e-5f;
constexpr float SLOPE_ = 0.2f;
}

// ---------------------------------------------------------------------------
// Scratch buffers (device globals -- no allocation allowed)
// ---------------------------------------------------------------------------
__device__ float    g_xlr  [(size_t)N_ * 320];   // [N][320]: cols 0..159 = xl, 160..319 = xr
__device__ float    g_score[(size_t)E_ * H_];    // scores, then ex (in place)
__device__ unsigned g_mx   [N_ * H_];            // ordered-uint encoded segment max
__device__ float    g_denom[N_ * H_];
__device__ float    g_agg  [(size_t)N_ * D_];    // attention agg, later reused for MLP2 out
__device__ float    g_out1 [(size_t)N_ * D_];    // after first LN (residual for final LN)
__device__ float    g_hid  [(size_t)N_ * HID_];
__device__ float    g_Wcat [D_ * 320];           // [Wl | Wr]
__device__ float    g_bcat [320];

// ---------------------------------------------------------------------------
// Helpers
// ---------------------------------------------------------------------------
__device__ __forceinline__ unsigned fenc(float f) {
    unsigned u = __float_as_uint(f);
    return (u & 0x80000000u) ? ~u : (u | 0x80000000u);
}
__device__ __forceinline__ float fdec(unsigned u) {
    return (u & 0x80000000u) ? __uint_as_float(u & 0x7FFFFFFFu)
                             : __uint_as_float(~u);
}

__device__ __forceinline__ float selu_f(float x) {
    const float a = 1.6732632423543772f;
    const float s = 1.0507009873554805f;
    return x > 0.f ? s * x : s * a * (__expf(x) - 1.f);
}

// packed f32x2 FMA: d = a * b + d   (exact fp32 semantics, 2 lanes per instr)
#define FMA_F32X2(d, a, b) \
    asm("fma.rn.f32x2 %0, %1, %2, %0;" : "+l"(d) : "l"(a), "l"(b))

__device__ __forceinline__ float lo32(unsigned long long v) {
    return __uint_as_float((unsigned)(v & 0xffffffffull));
}
__device__ __forceinline__ float hi32(unsigned long long v) {
    return __uint_as_float((unsigned)(v >> 32));
}

// ---------------------------------------------------------------------------
// Init: zero agg + denom, fill mx with encoded -inf
// ---------------------------------------------------------------------------
__global__ void init_k() {
    int i = blockIdx.x * blockDim.x + threadIdx.x;
    if (i < N_ * D_ / 4)
        reinterpret_cast<float4*>(g_agg)[i] = make_float4(0.f, 0.f, 0.f, 0.f);
    if (i < N_ * H_) {
        g_denom[i] = 0.f;
        g_mx[i]    = 0x007FFFFFu;   // fenc(-inf)
    }
}

__global__ void prep_w(const float* __restrict__ Wl, const float* __restrict__ bl,
                       const float* __restrict__ Wr, const float* __restrict__ br) {
    int i = blockIdx.x * blockDim.x + threadIdx.x;
    if (i < D_ * 320) {
        int k = i / 320, c = i - k * 320;
        g_Wcat[i] = (c < D_) ? Wl[k * D_ + c] : Wr[k * D_ + (c - D_)];
    }
    if (i < 320)
        g_bcat[i] = (i < D_) ? bl[i] : br[i - D_];
}

// ---------------------------------------------------------------------------
// SGEMM with packed f32x2 FMA (FFMA2).
// C[M,Nc] = A[M,K] @ B[K,Nc] + bias (+optional SELU)
// BM=128, BN=64, BK=32, 256 threads.
// Accumulators packed along ROW pairs: acc2[p][j] = {C[r0,j], C[r1,j]}.
//  - A pairs come free from the transposed As tile (consecutive rows adjacent).
//  - B stored DUPLICATED in smem ({b,b} pairs) so no packing movs at all.
// ---------------------------------------------------------------------------
template<bool DOSELU>
__global__ __launch_bounds__(256)
void sgemm_k(const float* __restrict__ A, const float* __restrict__ B,
             const float* __restrict__ bias, float* __restrict__ C,
             int M, int Nc, int K)
{
    constexpr int BM = 128, BN = 64, BK = 32, LDA = BM + 4;
    __shared__ float As [BK * LDA];      // A^T tile
    __shared__ float Bs2[BK * BN * 2];   // duplicated: Bs2[k][2n]=Bs2[k][2n+1]=B[k][n]

    const int tid = threadIdx.x;
    const int bm0 = blockIdx.y * BM;
    const int bn0 = blockIdx.x * BN;

    const int ra = tid >> 3;          // 0..31
    const int ka = (tid & 7) << 2;    // 0,4,...,28
    const int kb = tid >> 4;          // 0..15
    const int nb = (tid & 15) << 2;   // 0..60
    const int ty = tid >> 4;          // 0..15
    const int tx = tid & 15;          // 0..15

    unsigned long long acc2[4][4];
#pragma unroll
    for (int p = 0; p < 4; p++)
#pragma unroll
        for (int j = 0; j < 4; j++) acc2[p][j] = 0ull;  // {0.f,0.f}

    for (int k0 = 0; k0 < K; k0 += BK) {
        // --- A tile: coalesced load, transpose into smem
#pragma unroll
        for (int r = 0; r < 4; r++) {
            int row = bm0 + ra + r * 32;
            float4 v = make_float4(0.f, 0.f, 0.f, 0.f);
            if (row < M)
                v = *reinterpret_cast<const float4*>(A + (size_t)row * K + k0 + ka);
            int sm = ra + r * 32;
            As[(ka + 0) * LDA + sm] = v.x;
            As[(ka + 1) * LDA + sm] = v.y;
            As[(ka + 2) * LDA + sm] = v.z;
            As[(ka + 3) * LDA + sm] = v.w;
        }
        // --- B tile: load row-major, store duplicated pairs
        {
            int colb = bn0 + nb;
#pragma unroll
            for (int r = 0; r < 2; r++) {
                int k = kb + r * 16;
                float4 v = make_float4(0.f, 0.f, 0.f, 0.f);
                if (colb < Nc)
                    v = *reinterpret_cast<const float4*>(B + (size_t)(k0 + k) * Nc + colb);
                float4* q = reinterpret_cast<float4*>(&Bs2[k * (2 * BN) + 2 * nb]);
                q[0] = make_float4(v.x, v.x, v.y, v.y);
                q[1] = make_float4(v.z, v.z, v.w, v.w);
            }
        }
        __syncthreads();

#pragma unroll 8
        for (int kk = 0; kk < BK; kk++) {
            const unsigned long long* pa0 =
                reinterpret_cast<const unsigned long long*>(&As[kk * LDA + ty * 4]);
            const unsigned long long* pa1 =
                reinterpret_cast<const unsigned long long*>(&As[kk * LDA + 64 + ty * 4]);
            const unsigned long long* pb =
                reinterpret_cast<const unsigned long long*>(&Bs2[kk * (2 * BN) + 8 * tx]);
            unsigned long long ap[4];
            ap[0] = pa0[0];  ap[1] = pa0[1];   // rows (ty*4, ty*4+1), (ty*4+2, ty*4+3)
            ap[2] = pa1[0];  ap[3] = pa1[1];   // rows (+64 ...)
            unsigned long long bp[4];
            bp[0] = pb[0]; bp[1] = pb[1]; bp[2] = pb[2]; bp[3] = pb[3];
#pragma unroll
            for (int p = 0; p < 4; p++)
#pragma unroll
                for (int j = 0; j < 4; j++)
                    FMA_F32X2(acc2[p][j], ap[p], bp[j]);
        }
        __syncthreads();
    }

    // --- epilogue: unpack pairs, +bias (+SELU)
    int ncol = bn0 + tx * 4;
    if (ncol >= Nc) return;
    float4 bv = *reinterpret_cast<const float4*>(bias + ncol);
#pragma unroll
    for (int p = 0; p < 4; p++) {
        int rbase = bm0 + ((p < 2) ? (ty * 4 + 2 * p) : (64 + ty * 4 + 2 * (p - 2)));
        // row rbase   = lo halves; row rbase+1 = hi halves
        if (rbase < M) {
            float4 o = make_float4(lo32(acc2[p][0]) + bv.x, lo32(acc2[p][1]) + bv.y,
                                   lo32(acc2[p][2]) + bv.z, lo32(acc2[p][3]) + bv.w);
            if (DOSELU) {
                o.x = selu_f(o.x); o.y = selu_f(o.y);
                o.z = selu_f(o.z); o.w = selu_f(o.w);
            }
            *reinterpret_cast<float4*>(C + (size_t)rbase * Nc + ncol) = o;
        }
        if (rbase + 1 < M) {
            float4 o = make_float4(hi32(acc2[p][0]) + bv.x, hi32(acc2[p][1]) + bv.y,
                                   hi32(acc2[p][2]) + bv.z, hi32(acc2[p][3]) + bv.w);
            if (DOSELU) {
                o.x = selu_f(o.x); o.y = selu_f(o.y);
                o.z = selu_f(o.z); o.w = selu_f(o.w);
            }
            *reinterpret_cast<float4*>(C + (size_t)(rbase + 1) * Nc + ncol) = o;
        }
    }
}

// ---------------------------------------------------------------------------
// Edge pass 1 (v3): warp per (edge, head); head FIXED per warp.
// Lane l needs only We[k][h*32+l] (16 regs) + att[h*32+l] (1 reg):
// low register pressure -> ~50% occupancy, latency hidden.
// Launch with nw warps, nw % 5 == 0; warps_per_head = nw/5.
// ---------------------------------------------------------------------------
__global__ __launch_bounds__(256)
void edge_score_k(const int* __restrict__ ei, const float* __restrict__ eattr,
                  const float* __restrict__ We, const float* __restrict__ att)
{
    const int lane = threadIdx.x & 31;
    const int w    = (blockIdx.x * 256 + threadIdx.x) >> 5;
    const int nw   = (gridDim.x * 256) >> 5;
    const int wph  = nw / 5;            // warps per head (nw multiple of 5)
    const int h    = w / wph;           // 0..4
    const int e0   = w - h * wph;
    const int col  = h * 32 + lane;

    const float att_r = __ldg(&att[col]);
    float we_r[ED_];
#pragma unroll
    for (int k = 0; k < ED_; k++)
        we_r[k] = __ldg(&We[k * D_ + col]);

    for (int e = e0; e < E_; e += wph) {
        int src = __ldg(&ei[e]);          // uniform -> broadcast
        int dst = __ldg(&ei[E_ + e]);

        float v = g_xlr[(size_t)src * 320 + col] +
                  g_xlr[(size_t)dst * 320 + 160 + col];

        const float4* ep = reinterpret_cast<const float4*>(eattr + (size_t)e * ED_);
        float4 e0v = __ldg(ep + 0);
        float4 e1v = __ldg(ep + 1);
        float4 e2v = __ldg(ep + 2);
        float4 e3v = __ldg(ep + 3);
        v = fmaf(e0v.x, we_r[0],  v); v = fmaf(e0v.y, we_r[1],  v);
        v = fmaf(e0v.z, we_r[2],  v); v = fmaf(e0v.w, we_r[3],  v);
        v = fmaf(e1v.x, we_r[4],  v); v = fmaf(e1v.y, we_r[5],  v);
        v = fmaf(e1v.z, we_r[6],  v); v = fmaf(e1v.w, we_r[7],  v);
        v = fmaf(e2v.x, we_r[8],  v); v = fmaf(e2v.y, we_r[9],  v);
        v = fmaf(e2v.z, we_r[10], v); v = fmaf(e2v.w, we_r[11], v);
        v = fmaf(e3v.x, we_r[12], v); v = fmaf(e3v.y, we_r[13], v);
        v = fmaf(e3v.z, we_r[14], v); v = fmaf(e3v.w, we_r[15], v);

        float s = att_r * (v > 0.f ? v : SLOPE_ * v);
#pragma unroll
        for (int o = 16; o > 0; o >>= 1)
            s += __shfl_xor_sync(0xffffffffu, s, o);

        if (lane == 0) {
            g_score[(size_t)e * H_ + h] = s;
            atomicMax(&g_mx[(size_t)dst * H_ + h], fenc(s));
        }
    }
}

// ---------------------------------------------------------------------------
// Edge pass 2: one thread per edge -- single dst load, 5 exps, 5 atomics
// ---------------------------------------------------------------------------
__global__ void edge_exp_k(const int* __restrict__ ei)
{
    int e = blockIdx.x * blockDim.x + threadIdx.x;
    if (e >= E_) return;
    int dst = __ldg(&ei[E_ + e]);
    float*    sp  = g_score + (size_t)e * H_;
    unsigned* mxp = g_mx    + (size_t)dst * H_;
    float*    dp  = g_denom + (size_t)dst * H_;
#pragma unroll
    for (int h = 0; h < H_; h++) {
        float ex = __expf(sp[h] - fdec(mxp[h]));
        sp[h] = ex;
        atomicAdd(&dp[h], ex);
    }
}

// ---------------------------------------------------------------------------
// Edge pass 3: agg[dst] += alpha[e,h] * xl[src]  (vector f32x4 REDs)
// ---------------------------------------------------------------------------
__global__ __launch_bounds__(256)
void edge_agg_k(const int* __restrict__ ei)
{
    const int lane = threadIdx.x & 31;
    int w        = (blockIdx.x * 256 + threadIdx.x) >> 5;
    const int nw = (gridDim.x * 256) >> 5;

    for (int e = w; e < E_; e += nw) {
        int src = __ldg(&ei[e]);
        int dst = __ldg(&ei[E_ + e]);
        float al = 0.f;
        if (lane < H_)
            al = g_score[(size_t)e * H_ + lane] / g_denom[(size_t)dst * H_ + lane];
        float a0 = __shfl_sync(0xffffffffu, al, lane >> 3);  // head of my group
        float a4 = __shfl_sync(0xffffffffu, al, 4);          // head 4

        const float4* xl4 = reinterpret_cast<const float4*>(g_xlr + (size_t)src * 320);
        float4*       ag4 = reinterpret_cast<float4*>(g_agg + (size_t)dst * 160);
        {
            float4 v = __ldg(xl4 + lane);
            asm volatile("red.global.add.v4.f32 [%0], {%1,%2,%3,%4};" ::
                         "l"(ag4 + lane),
                         "f"(a0 * v.x), "f"(a0 * v.y), "f"(a0 * v.z), "f"(a0 * v.w)
                         : "memory");
        }
        if (lane < 8) {
            float4 v = __ldg(xl4 + 32 + lane);
            asm volatile("red.global.add.v4.f32 [%0], {%1,%2,%3,%4};" ::
                         "l"(ag4 + 32 + lane),
                         "f"(a4 * v.x), "f"(a4 * v.y), "f"(a4 * v.z), "f"(a4 * v.w)
                         : "memory");
        }
    }
}

// ---------------------------------------------------------------------------
// LayerNorms (warp per row)
// ---------------------------------------------------------------------------
__global__ void ln1_k(const float* __restrict__ x, const float* __restrict__ bgat,
                      const float* __restrict__ g, const float* __restrict__ b)
{
    const int lane = threadIdx.x & 31;
    int row = (blockIdx.x * blockDim.x + threadIdx.x) >> 5;
    if (row >= N_) return;
    const float* xr = x     + (size_t)row * D_;
    const float* ar = g_agg + (size_t)row * D_;
    float v[H_];
    float s = 0.f, s2 = 0.f;
#pragma unroll
    for (int h = 0; h < H_; h++) {
        int c = h * 32 + lane;
        float t = xr[c] + ar[c] + __ldg(&bgat[c]);
        v[h] = t; s += t; s2 = fmaf(t, t, s2);
    }
#pragma unroll
    for (int o = 16; o > 0; o >>= 1) {
        s  += __shfl_xor_sync(0xffffffffu, s,  o);
        s2 += __shfl_xor_sync(0xffffffffu, s2, o);
    }
    float mean = s * (1.f / D_);
    float var  = s2 * (1.f / D_) - mean * mean;
    float inv  = rsqrtf(var + EPS_);
    float* op = g_out1 + (size_t)row * D_;
#pragma unroll
    for (int h = 0; h < H_; h++) {
        int c = h * 32 + lane;
        op[c] = (v[h] - mean) * inv * __ldg(&g[c]) + __ldg(&b[c]);
    }
}

__global__ void ln_hid_k(const float* __restrict__ g, const float* __restrict__ b)
{
    const int lane = threadIdx.x & 31;
    int row = (blockIdx.x * blockDim.x + threadIdx.x) >> 5;
    if (row >= N_) return;
    float* hp = g_hid + (size_t)row * HID_;
    float4 v[4];
    float s = 0.f, s2 = 0.f;
#pragma unroll
    for (int j = 0; j < 4; j++) {
        v[j] = *reinterpret_cast<const float4*>(hp + j * 128 + lane * 4);
        s += v[j].x + v[j].y + v[j].z + v[j].w;
        s2 = fmaf(v[j].x, v[j].x, fmaf(v[j].y, v[j].y,
             fmaf(v[j].z, v[j].z, fmaf(v[j].w, v[j].w, s2))));
    }
#pragma unroll
    for (int o = 16; o > 0; o >>= 1) {
        s  += __shfl_xor_sync(0xffffffffu, s,  o);
        s2 += __shfl_xor_sync(0xffffffffu, s2, o);
    }
    float mean = s * (1.f / HID_);
    float var  = s2 * (1.f / HID_) - mean * mean;
    float inv  = rsqrtf(var + EPS_);
#pragma unroll
    for (int j = 0; j < 4; j++) {
        int c = j * 128 + lane * 4;
        float4 gg = __ldg(reinterpret_cast<const float4*>(g + c));
        float4 bb = __ldg(reinterpret_cast<const float4*>(b + c));
        float4 o;
        o.x = (v[j].x - mean) * inv * gg.x + bb.x;
        o.y = (v[j].y - mean) * inv * gg.y + bb.y;
        o.z = (v[j].z - mean) * inv * gg.z + bb.z;
        o.w = (v[j].w - mean) * inv * gg.w + bb.w;
        *reinterpret_cast<float4*>(hp + c) = o;
    }
}

__global__ void ln2_k(const float* __restrict__ g, const float* __restrict__ b,
                      float* __restrict__ out)
{
    const int lane = threadIdx.x & 31;
    int row = (blockIdx.x * blockDim.x + threadIdx.x) >> 5;
    if (row >= N_) return;
    const float* r1 = g_out1 + (size_t)row * D_;
    const float* r2 = g_agg  + (size_t)row * D_;
    float v[H_];
    float s = 0.f, s2 = 0.f;
#pragma unroll
    for (int h = 0; h < H_; h++) {
        int c = h * 32 + lane;
        float t = r1[c] + r2[c];
        v[h] = t; s += t; s2 = fmaf(t, t, s2);
    }
#pragma unroll
    for (int o = 16; o > 0; o >>= 1) {
        s  += __shfl_xor_sync(0xffffffffu, s,  o);
        s2 += __shfl_xor_sync(0xffffffffu, s2, o);
    }
    float mean = s * (1.f / D_);
    float var  = s2 * (1.f / D_) - mean * mean;
    float inv  = rsqrtf(var + EPS_);
    float* op = out + (size_t)row * D_;
#pragma unroll
    for (int h = 0; h < H_; h++) {
        int c = h * 32 + lane;
        op[c] = (v[h] - mean) * inv * __ldg(&g[c]) + __ldg(&b[c]);
    }
}

// ---------------------------------------------------------------------------
// Launch
// ---------------------------------------------------------------------------
extern "C" void kernel_launch(void* const* d_in, const int* in_sizes, int n_in,
                              void* d_out, int out_size)
{
    const float* x     = (const float*)d_in[0];
    const int*   ei    = (const int*)  d_in[1];
    const float* eattr = (const float*)d_in[2];
    const float* Wl    = (const float*)d_in[5];
    const float* bl    = (const float*)d_in[6];
    const float* Wr    = (const float*)d_in[7];
    const float* br    = (const float*)d_in[8];
    const float* We    = (const float*)d_in[9];
    const float* att   = (const float*)d_in[10];
    const float* bgat  = (const float*)d_in[11];
    const float* g1    = (const float*)d_in[12];
    const float* b1    = (const float*)d_in[13];
    const float* Wm1   = (const float*)d_in[14];
    const float* bm1   = (const float*)d_in[15];
    const float* gm    = (const float*)d_in[16];
    const float* bm    = (const float*)d_in[17];
    const float* Wm2   = (const float*)d_in[18];
    const float* bm2   = (const float*)d_in[19];
    const float* g2    = (const float*)d_in[20];
    const float* b2    = (const float*)d_in[21];
    float* out = (float*)d_out;

    float *xlr, *Wcat, *bcat, *out1, *hid, *agg;
    cudaGetSymbolAddress((void**)&xlr,  g_xlr);
    cudaGetSymbolAddress((void**)&Wcat, g_Wcat);
    cudaGetSymbolAddress((void**)&bcat, g_bcat);
    cudaGetSymbolAddress((void**)&out1, g_out1);
    cudaGetSymbolAddress((void**)&hid,  g_hid);
    cudaGetSymbolAddress((void**)&agg,  g_agg);

    init_k<<<(N_ * D_ / 4 + 255) / 256, 256>>>();
    prep_w<<<(D_ * 320 + 255) / 256, 256>>>(Wl, bl, Wr, br);

    // xl|xr = x @ [Wl|Wr] + [bl|br]   -> g_xlr [N,320]
    sgemm_k<false><<<dim3(320 / 64, (N_ + 127) / 128), 256>>>(
        x, Wcat, bcat, xlr, N_, 320, D_);

    // GATv2 attention (edge_score: 1480 blocks -> 11840 warps = 5 * 2368)
    edge_score_k<<<1480, 256>>>(ei, eattr, We, att);
    edge_exp_k<<<(E_ + 255) / 256, 256>>>(ei);
    edge_agg_k<<<1184, 256>>>(ei);

    // out1 = LN(x + agg + b_gat)
    ln1_k<<<(N_ + 7) / 8, 256>>>(x, bgat, g1, b1);

    // hid = selu(out1 @ W_m1 + b_m1), then LN in place
    sgemm_k<true><<<dim3(HID_ / 64, (N_ + 127) / 128), 256>>>(
        out1, Wm1, bm1, hid, N_, HID_, D_);
    ln_hid_k<<<(N_ + 7) / 8, 256>>>(gm, bm);

    // mlp = hid @ W_m2 + b_m2  (reuse g_agg)
    sgemm_k<false><<<dim3((D_ + 63) / 64, (N_ + 127) / 128), 256>>>(
        hid, Wm2, bm2, agg, N_, D_, HID_);

    // out = LN(out1 + mlp)
    ln2_k<<<(N_ + 7) / 8, 256>>>(g2, b2, out);
}

// round 9
// speedup vs baseline: 1.2079x; 1.2079x over previous
#include <cuda_runtime.h>
#include <cstdint>
#include <cstddef>

// ---------------------------------------------------------------------------
// Problem constants
// ---------------------------------------------------------------------------
namespace {
constexpr int N_   = 50000;
constexpr int D_   = 160;     // = H*C
constexpr int H_   = 5;
constexpr int E_   = 800000;
constexpr int ED_  = 16;
constexpr int HID_ = 512;
constexpr float EPS_   = 1e-5f;
constexpr float SLOPE_ = 0.2f;
}

// ---------------------------------------------------------------------------
// Scratch buffers (device globals -- no allocation allowed)
// ---------------------------------------------------------------------------
__device__ float    g_xlr  [(size_t)N_ * 320];   // [N][320]: cols 0..159 = xl, 160..319 = xr
__device__ float    g_score[(size_t)E_ * H_];    // scores, then ex (in place)
__device__ unsigned g_mx   [N_ * H_];            // ordered-uint encoded segment max
__device__ float    g_denom[N_ * H_];
__device__ float    g_agg  [(size_t)N_ * D_];    // attention agg, later reused for MLP2 out
__device__ float    g_out1 [(size_t)N_ * D_];    // after first LN (residual for final LN)
__device__ float    g_hid  [(size_t)N_ * HID_];
__device__ float    g_Wcat [D_ * 320];           // [Wl | Wr]
__device__ float    g_bcat [320];

// ---------------------------------------------------------------------------
// Helpers
// ---------------------------------------------------------------------------
__device__ __forceinline__ unsigned fenc(float f) {
    unsigned u = __float_as_uint(f);
    return (u & 0x80000000u) ? ~u : (u | 0x80000000u);
}
__device__ __forceinline__ float fdec(unsigned u) {
    return (u & 0x80000000u) ? __uint_as_float(u & 0x7FFFFFFFu)
                             : __uint_as_float(~u);
}

__device__ __forceinline__ float selu_f(float x) {
    const float a = 1.6732632423543772f;
    const float s = 1.0507009873554805f;
    return x > 0.f ? s * x : s * a * (__expf(x) - 1.f);
}

// ---------------------------------------------------------------------------
// Init: zero agg + denom, fill mx with encoded -inf
// ---------------------------------------------------------------------------
__global__ void init_k() {
    int i = blockIdx.x * blockDim.x + threadIdx.x;
    if (i < N_ * D_ / 4)
        reinterpret_cast<float4*>(g_agg)[i] = make_float4(0.f, 0.f, 0.f, 0.f);
    if (i < N_ * H_) {
        g_denom[i] = 0.f;
        g_mx[i]    = 0x007FFFFFu;   // fenc(-inf)
    }
}

__global__ void prep_w(const float* __restrict__ Wl, const float* __restrict__ bl,
                       const float* __restrict__ Wr, const float* __restrict__ br) {
    int i = blockIdx.x * blockDim.x + threadIdx.x;
    if (i < D_ * 320) {
        int k = i / 320, c = i - k * 320;
        g_Wcat[i] = (c < D_) ? Wl[k * D_ + c] : Wr[k * D_ + (c - D_)];
    }
    if (i < 320)
        g_bcat[i] = (i < D_) ? bl[i] : br[i - D_];
}

// ---------------------------------------------------------------------------
// SGEMM (Round-7 proven version): C = A @ B + bias (+optional SELU)
// BM=128, BN=64, BK=32, 256 threads, 8x4 microtile, scalar FFMA.
// ---------------------------------------------------------------------------
template<bool DOSELU>
__global__ __launch_bounds__(256)
void sgemm_k(const float* __restrict__ A, const float* __restrict__ B,
             const float* __restrict__ bias, float* __restrict__ C,
             int M, int Nc, int K)
{
    constexpr int BM = 128, BN = 64, BK = 32, LDA = BM + 4;
    __shared__ float As[BK * LDA];
    __shared__ float Bs[BK * BN];

    const int tid = threadIdx.x;
    const int bm0 = blockIdx.y * BM;
    const int bn0 = blockIdx.x * BN;

    const int ra = tid >> 3;
    const int ka = (tid & 7) << 2;
    const int kb = tid >> 4;
    const int nb = (tid & 15) << 2;
    const int ty = tid >> 4;
    const int tx = tid & 15;

    float acc[8][4];
#pragma unroll
    for (int i = 0; i < 8; i++)
#pragma unroll
        for (int j = 0; j < 4; j++) acc[i][j] = 0.f;

    for (int k0 = 0; k0 < K; k0 += BK) {
#pragma unroll
        for (int r = 0; r < 4; r++) {
            int row = bm0 + ra + r * 32;
            float4 v = make_float4(0.f, 0.f, 0.f, 0.f);
            if (row < M)
                v = *reinterpret_cast<const float4*>(A + (size_t)row * K + k0 + ka);
            int sm = ra + r * 32;
            As[(ka + 0) * LDA + sm] = v.x;
            As[(ka + 1) * LDA + sm] = v.y;
            As[(ka + 2) * LDA + sm] = v.z;
            As[(ka + 3) * LDA + sm] = v.w;
        }
        {
            int colb = bn0 + nb;
#pragma unroll
            for (int r = 0; r < 2; r++) {
                int k = kb + r * 16;
                float4 v = make_float4(0.f, 0.f, 0.f, 0.f);
                if (colb < Nc)
                    v = *reinterpret_cast<const float4*>(B + (size_t)(k0 + k) * Nc + colb);
                *reinterpret_cast<float4*>(&Bs[k * BN + nb]) = v;
            }
        }
        __syncthreads();

#pragma unroll 8
        for (int kk = 0; kk < BK; kk++) {
            float4 a0 = *reinterpret_cast<const float4*>(&As[kk * LDA + ty * 4]);
            float4 a1 = *reinterpret_cast<const float4*>(&As[kk * LDA + 64 + ty * 4]);
            float4 b4 = *reinterpret_cast<const float4*>(&Bs[kk * BN + tx * 4]);
            float ar[8]  = {a0.x, a0.y, a0.z, a0.w, a1.x, a1.y, a1.z, a1.w};
            float brg[4] = {b4.x, b4.y, b4.z, b4.w};
#pragma unroll
            for (int i = 0; i < 8; i++)
#pragma unroll
                for (int j = 0; j < 4; j++)
                    acc[i][j] = fmaf(ar[i], brg[j], acc[i][j]);
        }
        __syncthreads();
    }

    int ncol = bn0 + tx * 4;
    if (ncol >= Nc) return;
    float4 bv = *reinterpret_cast<const float4*>(bias + ncol);
#pragma unroll
    for (int i = 0; i < 8; i++) {
        int row = bm0 + ((i < 4) ? (ty * 4 + i) : (64 + ty * 4 + (i - 4)));
        if (row < M) {
            float4 o = make_float4(acc[i][0] + bv.x, acc[i][1] + bv.y,
                                   acc[i][2] + bv.z, acc[i][3] + bv.w);
            if (DOSELU) {
                o.x = selu_f(o.x); o.y = selu_f(o.y);
                o.z = selu_f(o.z); o.w = selu_f(o.w);
            }
            *reinterpret_cast<float4*>(C + (size_t)row * Nc + ncol) = o;
        }
    }
}

// ---------------------------------------------------------------------------
// Edge pass 1 (Round-8 version, kept): warp per (edge, head); head fixed per
// warp. Lane l needs only We[k][h*32+l] (16 regs) + att[h*32+l] (1 reg):
// low register pressure -> ~44% occupancy, latency hidden.
// ---------------------------------------------------------------------------
__global__ __launch_bounds__(256)
void edge_score_k(const int* __restrict__ ei, const float* __restrict__ eattr,
                  const float* __restrict__ We, const float* __restrict__ att)
{
    const int lane = threadIdx.x & 31;
    const int w    = (blockIdx.x * 256 + threadIdx.x) >> 5;
    const int nw   = (gridDim.x * 256) >> 5;
    const int wph  = nw / 5;            // warps per head (nw multiple of 5)
    const int h    = w / wph;           // 0..4
    const int e0   = w - h * wph;
    const int col  = h * 32 + lane;

    const float att_r = __ldg(&att[col]);
    float we_r[ED_];
#pragma unroll
    for (int k = 0; k < ED_; k++)
        we_r[k] = __ldg(&We[k * D_ + col]);

    for (int e = e0; e < E_; e += wph) {
        int src = __ldg(&ei[e]);          // uniform -> broadcast
        int dst = __ldg(&ei[E_ + e]);

        float v = g_xlr[(size_t)src * 320 + col] +
                  g_xlr[(size_t)dst * 320 + 160 + col];

        const float4* ep = reinterpret_cast<const float4*>(eattr + (size_t)e * ED_);
        float4 e0v = __ldg(ep + 0);
        float4 e1v = __ldg(ep + 1);
        float4 e2v = __ldg(ep + 2);
        float4 e3v = __ldg(ep + 3);
        v = fmaf(e0v.x, we_r[0],  v); v = fmaf(e0v.y, we_r[1],  v);
        v = fmaf(e0v.z, we_r[2],  v); v = fmaf(e0v.w, we_r[3],  v);
        v = fmaf(e1v.x, we_r[4],  v); v = fmaf(e1v.y, we_r[5],  v);
        v = fmaf(e1v.z, we_r[6],  v); v = fmaf(e1v.w, we_r[7],  v);
        v = fmaf(e2v.x, we_r[8],  v); v = fmaf(e2v.y, we_r[9],  v);
        v = fmaf(e2v.z, we_r[10], v); v = fmaf(e2v.w, we_r[11], v);
        v = fmaf(e3v.x, we_r[12], v); v = fmaf(e3v.y, we_r[13], v);
        v = fmaf(e3v.z, we_r[14], v); v = fmaf(e3v.w, we_r[15], v);

        float s = att_r * (v > 0.f ? v : SLOPE_ * v);
#pragma unroll
        for (int o = 16; o > 0; o >>= 1)
            s += __shfl_xor_sync(0xffffffffu, s, o);

        if (lane == 0) {
            g_score[(size_t)e * H_ + h] = s;
            atomicMax(&g_mx[(size_t)dst * H_ + h], fenc(s));
        }
    }
}

// ---------------------------------------------------------------------------
// Edge pass 2: one thread per edge -- single dst load, 5 exps, 5 atomics
// ---------------------------------------------------------------------------
__global__ void edge_exp_k(const int* __restrict__ ei)
{
    int e = blockIdx.x * blockDim.x + threadIdx.x;
    if (e >= E_) return;
    int dst = __ldg(&ei[E_ + e]);
    float*    sp  = g_score + (size_t)e * H_;
    unsigned* mxp = g_mx    + (size_t)dst * H_;
    float*    dp  = g_denom + (size_t)dst * H_;
#pragma unroll
    for (int h = 0; h < H_; h++) {
        float ex = __expf(sp[h] - fdec(mxp[h]));
        sp[h] = ex;
        atomicAdd(&dp[h], ex);
    }
}

// ---------------------------------------------------------------------------
// Edge pass 3: agg[dst] += alpha[e,h] * xl[src]  (vector f32x4 REDs)
// ---------------------------------------------------------------------------
__global__ __launch_bounds__(256)
void edge_agg_k(const int* __restrict__ ei)
{
    const int lane = threadIdx.x & 31;
    int w        = (blockIdx.x * 256 + threadIdx.x) >> 5;
    const int nw = (gridDim.x * 256) >> 5;

    for (int e = w; e < E_; e += nw) {
        int src = __ldg(&ei[e]);
        int dst = __ldg(&ei[E_ + e]);
        float al = 0.f;
        if (lane < H_)
            al = g_score[(size_t)e * H_ + lane] / g_denom[(size_t)dst * H_ + lane];
        float a0 = __shfl_sync(0xffffffffu, al, lane >> 3);  // head of my group
        float a4 = __shfl_sync(0xffffffffu, al, 4);          // head 4

        const float4* xl4 = reinterpret_cast<const float4*>(g_xlr + (size_t)src * 320);
        float4*       ag4 = reinterpret_cast<float4*>(g_agg + (size_t)dst * 160);
        {
            float4 v = __ldg(xl4 + lane);
            asm volatile("red.global.add.v4.f32 [%0], {%1,%2,%3,%4};" ::
                         "l"(ag4 + lane),
                         "f"(a0 * v.x), "f"(a0 * v.y), "f"(a0 * v.z), "f"(a0 * v.w)
                         : "memory");
        }
        if (lane < 8) {
            float4 v = __ldg(xl4 + 32 + lane);
            asm volatile("red.global.add.v4.f32 [%0], {%1,%2,%3,%4};" ::
                         "l"(ag4 + 32 + lane),
                         "f"(a4 * v.x), "f"(a4 * v.y), "f"(a4 * v.z), "f"(a4 * v.w)
                         : "memory");
        }
    }
}

// ---------------------------------------------------------------------------
// LayerNorms (warp per row)
// ---------------------------------------------------------------------------
__global__ void ln1_k(const float* __restrict__ x, const float* __restrict__ bgat,
                      const float* __restrict__ g, const float* __restrict__ b)
{
    const int lane = threadIdx.x & 31;
    int row = (blockIdx.x * blockDim.x + threadIdx.x) >> 5;
    if (row >= N_) return;
    const float* xr = x     + (size_t)row * D_;
    const float* ar = g_agg + (size_t)row * D_;
    float v[H_];
    float s = 0.f, s2 = 0.f;
#pragma unroll
    for (int h = 0; h < H_; h++) {
        int c = h * 32 + lane;
        float t = xr[c] + ar[c] + __ldg(&bgat[c]);
        v[h] = t; s += t; s2 = fmaf(t, t, s2);
    }
#pragma unroll
    for (int o = 16; o > 0; o >>= 1) {
        s  += __shfl_xor_sync(0xffffffffu, s,  o);
        s2 += __shfl_xor_sync(0xffffffffu, s2, o);
    }
    float mean = s * (1.f / D_);
    float var  = s2 * (1.f / D_) - mean * mean;
    float inv  = rsqrtf(var + EPS_);
    float* op = g_out1 + (size_t)row * D_;
#pragma unroll
    for (int h = 0; h < H_; h++) {
        int c = h * 32 + lane;
        op[c] = (v[h] - mean) * inv * __ldg(&g[c]) + __ldg(&b[c]);
    }
}

__global__ void ln_hid_k(const float* __restrict__ g, const float* __restrict__ b)
{
    const int lane = threadIdx.x & 31;
    int row = (blockIdx.x * blockDim.x + threadIdx.x) >> 5;
    if (row >= N_) return;
    float* hp = g_hid + (size_t)row * HID_;
    float4 v[4];
    float s = 0.f, s2 = 0.f;
#pragma unroll
    for (int j = 0; j < 4; j++) {
        v[j] = *reinterpret_cast<const float4*>(hp + j * 128 + lane * 4);
        s += v[j].x + v[j].y + v[j].z + v[j].w;
        s2 = fmaf(v[j].x, v[j].x, fmaf(v[j].y, v[j].y,
             fmaf(v[j].z, v[j].z, fmaf(v[j].w, v[j].w, s2))));
    }
#pragma unroll
    for (int o = 16; o > 0; o >>= 1) {
        s  += __shfl_xor_sync(0xffffffffu, s,  o);
        s2 += __shfl_xor_sync(0xffffffffu, s2, o);
    }
    float mean = s * (1.f / HID_);
    float var  = s2 * (1.f / HID_) - mean * mean;
    float inv  = rsqrtf(var + EPS_);
#pragma unroll
    for (int j = 0; j < 4; j++) {
        int c = j * 128 + lane * 4;
        float4 gg = __ldg(reinterpret_cast<const float4*>(g + c));
        float4 bb = __ldg(reinterpret_cast<const float4*>(b + c));
        float4 o;
        o.x = (v[j].x - mean) * inv * gg.x + bb.x;
        o.y = (v[j].y - mean) * inv * gg.y + bb.y;
        o.z = (v[j].z - mean) * inv * gg.z + bb.z;
        o.w = (v[j].w - mean) * inv * gg.w + bb.w;
        *reinterpret_cast<float4*>(hp + c) = o;
    }
}

__global__ void ln2_k(const float* __restrict__ g, const float* __restrict__ b,
                      float* __restrict__ out)
{
    const int lane = threadIdx.x & 31;
    int row = (blockIdx.x * blockDim.x + threadIdx.x) >> 5;
    if (row >= N_) return;
    const float* r1 = g_out1 + (size_t)row * D_;
    const float* r2 = g_agg  + (size_t)row * D_;
    float v[H_];
    float s = 0.f, s2 = 0.f;
#pragma unroll
    for (int h = 0; h < H_; h++) {
        int c = h * 32 + lane;
        float t = r1[c] + r2[c];
        v[h] = t; s += t; s2 = fmaf(t, t, s2);
    }
#pragma unroll
    for (int o = 16; o > 0; o >>= 1) {
        s  += __shfl_xor_sync(0xffffffffu, s,  o);
        s2 += __shfl_xor_sync(0xffffffffu, s2, o);
    }
    float mean = s * (1.f / D_);
    float var  = s2 * (1.f / D_) - mean * mean;
    float inv  = rsqrtf(var + EPS_);
    float* op = out + (size_t)row * D_;
#pragma unroll
    for (int h = 0; h < H_; h++) {
        int c = h * 32 + lane;
        op[c] = (v[h] - mean) * inv * __ldg(&g[c]) + __ldg(&b[c]);
    }
}

// ---------------------------------------------------------------------------
// Launch
// ---------------------------------------------------------------------------
extern "C" void kernel_launch(void* const* d_in, const int* in_sizes, int n_in,
                              void* d_out, int out_size)
{
    const float* x     = (const float*)d_in[0];
    const int*   ei    = (const int*)  d_in[1];
    const float* eattr = (const float*)d_in[2];
    const float* Wl    = (const float*)d_in[5];
    const float* bl    = (const float*)d_in[6];
    const float* Wr    = (const float*)d_in[7];
    const float* br    = (const float*)d_in[8];
    const float* We    = (const float*)d_in[9];
    const float* att   = (const float*)d_in[10];
    const float* bgat  = (const float*)d_in[11];
    const float* g1    = (const float*)d_in[12];
    const float* b1    = (const float*)d_in[13];
    const float* Wm1   = (const float*)d_in[14];
    const float* bm1   = (const float*)d_in[15];
    const float* gm    = (const float*)d_in[16];
    const float* bm    = (const float*)d_in[17];
    const float* Wm2   = (const float*)d_in[18];
    const float* bm2   = (const float*)d_in[19];
    const float* g2    = (const float*)d_in[20];
    const float* b2    = (const float*)d_in[21];
    float* out = (float*)d_out;

    float *xlr, *Wcat, *bcat, *out1, *hid, *agg;
    cudaGetSymbolAddress((void**)&xlr,  g_xlr);
    cudaGetSymbolAddress((void**)&Wcat, g_Wcat);
    cudaGetSymbolAddress((void**)&bcat, g_bcat);
    cudaGetSymbolAddress((void**)&out1, g_out1);
    cudaGetSymbolAddress((void**)&hid,  g_hid);
    cudaGetSymbolAddress((void**)&agg,  g_agg);

    init_k<<<(N_ * D_ / 4 + 255) / 256, 256>>>();
    prep_w<<<(D_ * 320 + 255) / 256, 256>>>(Wl, bl, Wr, br);

    // xl|xr = x @ [Wl|Wr] + [bl|br]   -> g_xlr [N,320]
    sgemm_k<false><<<dim3(320 / 64, (N_ + 127) / 128), 256>>>(
        x, Wcat, bcat, xlr, N_, 320, D_);

    // GATv2 attention (edge_score: 1480 blocks -> 11840 warps = 5 * 2368)
    edge_score_k<<<1480, 256>>>(ei, eattr, We, att);
    edge_exp_k<<<(E_ + 255) / 256, 256>>>(ei);
    edge_agg_k<<<1184, 256>>>(ei);

    // out1 = LN(x + agg + b_gat)
    ln1_k<<<(N_ + 7) / 8, 256>>>(x, bgat, g1, b1);

    // hid = selu(out1 @ W_m1 + b_m1), then LN in place
    sgemm_k<true><<<dim3(HID_ / 64, (N_ + 127) / 128), 256>>>(
        out1, Wm1, bm1, hid, N_, HID_, D_);
    ln_hid_k<<<(N_ + 7) / 8, 256>>>(gm, bm);

    // mlp = hid @ W_m2 + b_m2  (reuse g_agg)
    sgemm_k<false><<<dim3((D_ + 63) / 64, (N_ + 127) / 128), 256>>>(
        hid, Wm2, bm2, agg, N_, D_, HID_);

    // out = LN(out1 + mlp)
    ln2_k<<<(N_ + 7) / 8, 256>>>(g2, b2, out);
}

// round 10
// speedup vs baseline: 1.2314x; 1.0195x over previous
#include <cuda_runtime.h>
#include <cstdint>
#include <cstddef>

// ---------------------------------------------------------------------------
// Problem constants
// ---------------------------------------------------------------------------
namespace {
constexpr int N_   = 50000;
constexpr int D_   = 160;     // = H*C
constexpr int H_   = 5;
constexpr int E_   = 800000;
constexpr int ED_  = 16;
constexpr int HID_ = 512;
constexpr float EPS_   = 1e-5f;
constexpr float SLOPE_ = 0.2f;
}

// ---------------------------------------------------------------------------
// Scratch buffers (device globals -- no allocation allowed)
// ---------------------------------------------------------------------------
__device__ float    g_xlr  [(size_t)N_ * 320];   // [N][320]: cols 0..159 = xl, 160..319 = xr
__device__ float    g_score[(size_t)E_ * H_];    // scores, then ex (in place)
__device__ unsigned g_mx   [N_ * H_];            // ordered-uint encoded segment max
__device__ float    g_denom[N_ * H_];
__device__ float    g_agg  [(size_t)N_ * D_];    // attention agg, later reused for MLP2 out
__device__ float    g_out1 [(size_t)N_ * D_];    // after first LN (residual for final LN)
__device__ float    g_hid  [(size_t)N_ * HID_];
__device__ float    g_Wcat [D_ * 320];           // [Wl | Wr]
__device__ float    g_bcat [320];

// ---------------------------------------------------------------------------
// Helpers
// ---------------------------------------------------------------------------
__device__ __forceinline__ unsigned fenc(float f) {
    unsigned u = __float_as_uint(f);
    return (u & 0x80000000u) ? ~u : (u | 0x80000000u);
}
__device__ __forceinline__ float fdec(unsigned u) {
    return (u & 0x80000000u) ? __uint_as_float(u & 0x7FFFFFFFu)
                             : __uint_as_float(~u);
}

__device__ __forceinline__ float selu_f(float x) {
    const float a = 1.6732632423543772f;
    const float s = 1.0507009873554805f;
    return x > 0.f ? s * x : s * a * (__expf(x) - 1.f);
}

// ---------------------------------------------------------------------------
// Init: zero agg + denom, fill mx with encoded -inf
// ---------------------------------------------------------------------------
__global__ void init_k() {
    int i = blockIdx.x * blockDim.x + threadIdx.x;
    if (i < N_ * D_ / 4)
        reinterpret_cast<float4*>(g_agg)[i] = make_float4(0.f, 0.f, 0.f, 0.f);
    if (i < N_ * H_) {
        g_denom[i] = 0.f;
        g_mx[i]    = 0x007FFFFFu;   // fenc(-inf)
    }
}

__global__ void prep_w(const float* __restrict__ Wl, const float* __restrict__ bl,
                       const float* __restrict__ Wr, const float* __restrict__ br) {
    int i = blockIdx.x * blockDim.x + threadIdx.x;
    if (i < D_ * 320) {
        int k = i / 320, c = i - k * 320;
        g_Wcat[i] = (c < D_) ? Wl[k * D_ + c] : Wr[k * D_ + (c - D_)];
    }
    if (i < 320)
        g_bcat[i] = (i < D_) ? bl[i] : br[i - D_];
}

// ---------------------------------------------------------------------------
// SGEMM (Round-7 proven version): C = A @ B + bias (+optional SELU)
// BM=128, BN=64, BK=32, 256 threads, 8x4 microtile, scalar FFMA.
// ---------------------------------------------------------------------------
template<bool DOSELU>
__global__ __launch_bounds__(256)
void sgemm_k(const float* __restrict__ A, const float* __restrict__ B,
             const float* __restrict__ bias, float* __restrict__ C,
             int M, int Nc, int K)
{
    constexpr int BM = 128, BN = 64, BK = 32, LDA = BM + 4;
    __shared__ float As[BK * LDA];
    __shared__ float Bs[BK * BN];

    const int tid = threadIdx.x;
    const int bm0 = blockIdx.y * BM;
    const int bn0 = blockIdx.x * BN;

    const int ra = tid >> 3;
    const int ka = (tid & 7) << 2;
    const int kb = tid >> 4;
    const int nb = (tid & 15) << 2;
    const int ty = tid >> 4;
    const int tx = tid & 15;

    float acc[8][4];
#pragma unroll
    for (int i = 0; i < 8; i++)
#pragma unroll
        for (int j = 0; j < 4; j++) acc[i][j] = 0.f;

    for (int k0 = 0; k0 < K; k0 += BK) {
#pragma unroll
        for (int r = 0; r < 4; r++) {
            int row = bm0 + ra + r * 32;
            float4 v = make_float4(0.f, 0.f, 0.f, 0.f);
            if (row < M)
                v = *reinterpret_cast<const float4*>(A + (size_t)row * K + k0 + ka);
            int sm = ra + r * 32;
            As[(ka + 0) * LDA + sm] = v.x;
            As[(ka + 1) * LDA + sm] = v.y;
            As[(ka + 2) * LDA + sm] = v.z;
            As[(ka + 3) * LDA + sm] = v.w;
        }
        {
            int colb = bn0 + nb;
#pragma unroll
            for (int r = 0; r < 2; r++) {
                int k = kb + r * 16;
                float4 v = make_float4(0.f, 0.f, 0.f, 0.f);
                if (colb < Nc)
                    v = *reinterpret_cast<const float4*>(B + (size_t)(k0 + k) * Nc + colb);
                *reinterpret_cast<float4*>(&Bs[k * BN + nb]) = v;
            }
        }
        __syncthreads();

#pragma unroll 8
        for (int kk = 0; kk < BK; kk++) {
            float4 a0 = *reinterpret_cast<const float4*>(&As[kk * LDA + ty * 4]);
            float4 a1 = *reinterpret_cast<const float4*>(&As[kk * LDA + 64 + ty * 4]);
            float4 b4 = *reinterpret_cast<const float4*>(&Bs[kk * BN + tx * 4]);
            float ar[8]  = {a0.x, a0.y, a0.z, a0.w, a1.x, a1.y, a1.z, a1.w};
            float brg[4] = {b4.x, b4.y, b4.z, b4.w};
#pragma unroll
            for (int i = 0; i < 8; i++)
#pragma unroll
                for (int j = 0; j < 4; j++)
                    acc[i][j] = fmaf(ar[i], brg[j], acc[i][j]);
        }
        __syncthreads();
    }

    int ncol = bn0 + tx * 4;
    if (ncol >= Nc) return;
    float4 bv = *reinterpret_cast<const float4*>(bias + ncol);
#pragma unroll
    for (int i = 0; i < 8; i++) {
        int row = bm0 + ((i < 4) ? (ty * 4 + i) : (64 + ty * 4 + (i - 4)));
        if (row < M) {
            float4 o = make_float4(acc[i][0] + bv.x, acc[i][1] + bv.y,
                                   acc[i][2] + bv.z, acc[i][3] + bv.w);
            if (DOSELU) {
                o.x = selu_f(o.x); o.y = selu_f(o.y);
                o.z = selu_f(o.z); o.w = selu_f(o.w);
            }
            *reinterpret_cast<float4*>(C + (size_t)row * Nc + ncol) = o;
        }
    }
}

// ---------------------------------------------------------------------------
// Edge pass 1 (Round-8 version, kept): warp per (edge, head); head fixed per
// warp. Lane l needs only We[k][h*32+l] (16 regs) + att[h*32+l] (1 reg):
// low register pressure -> ~44% occupancy, latency hidden.
// ---------------------------------------------------------------------------
__global__ __launch_bounds__(256)
void edge_score_k(const int* __restrict__ ei, const float* __restrict__ eattr,
                  const float* __restrict__ We, const float* __restrict__ att)
{
    const int lane = threadIdx.x & 31;
    const int w    = (blockIdx.x * 256 + threadIdx.x) >> 5;
    const int nw   = (gridDim.x * 256) >> 5;
    const int wph  = nw / 5;            // warps per head (nw multiple of 5)
    const int h    = w / wph;           // 0..4
    const int e0   = w - h * wph;
    const int col  = h * 32 + lane;

    const float att_r = __ldg(&att[col]);
    float we_r[ED_];
#pragma unroll
    for (int k = 0; k < ED_; k++)
        we_r[k] = __ldg(&We[k * D_ + col]);

    for (int e = e0; e < E_; e += wph) {
        int src = __ldg(&ei[e]);          // uniform -> broadcast
        int dst = __ldg(&ei[E_ + e]);

        float v = g_xlr[(size_t)src * 320 + col] +
                  g_xlr[(size_t)dst * 320 + 160 + col];

        const float4* ep = reinterpret_cast<const float4*>(eattr + (size_t)e * ED_);
        float4 e0v = __ldg(ep + 0);
        float4 e1v = __ldg(ep + 1);
        float4 e2v = __ldg(ep + 2);
        float4 e3v = __ldg(ep + 3);
        v = fmaf(e0v.x, we_r[0],  v); v = fmaf(e0v.y, we_r[1],  v);
        v = fmaf(e0v.z, we_r[2],  v); v = fmaf(e0v.w, we_r[3],  v);
        v = fmaf(e1v.x, we_r[4],  v); v = fmaf(e1v.y, we_r[5],  v);
        v = fmaf(e1v.z, we_r[6],  v); v = fmaf(e1v.w, we_r[7],  v);
        v = fmaf(e2v.x, we_r[8],  v); v = fmaf(e2v.y, we_r[9],  v);
        v = fmaf(e2v.z, we_r[10], v); v = fmaf(e2v.w, we_r[11], v);
        v = fmaf(e3v.x, we_r[12], v); v = fmaf(e3v.y, we_r[13], v);
        v = fmaf(e3v.z, we_r[14], v); v = fmaf(e3v.w, we_r[15], v);

        float s = att_r * (v > 0.f ? v : SLOPE_ * v);
#pragma unroll
        for (int o = 16; o > 0; o >>= 1)
            s += __shfl_xor_sync(0xffffffffu, s, o);

        if (lane == 0) {
            g_score[(size_t)e * H_ + h] = s;
            atomicMax(&g_mx[(size_t)dst * H_ + h], fenc(s));
        }
    }
}

// ---------------------------------------------------------------------------
// Edge pass 2: one thread per edge -- single dst load, 5 exps, 5 atomics
// ---------------------------------------------------------------------------
__global__ void edge_exp_k(const int* __restrict__ ei)
{
    int e = blockIdx.x * blockDim.x + threadIdx.x;
    if (e >= E_) return;
    int dst = __ldg(&ei[E_ + e]);
    float*    sp  = g_score + (size_t)e * H_;
    unsigned* mxp = g_mx    + (size_t)dst * H_;
    float*    dp  = g_denom + (size_t)dst * H_;
#pragma unroll
    for (int h = 0; h < H_; h++) {
        float ex = __expf(sp[h] - fdec(mxp[h]));
        sp[h] = ex;
        atomicAdd(&dp[h], ex);
    }
}

// ---------------------------------------------------------------------------
// Edge pass 3: agg[dst] += alpha[e,h] * xl[src]  (vector f32x4 REDs)
// ---------------------------------------------------------------------------
__global__ __launch_bounds__(256)
void edge_agg_k(const int* __restrict__ ei)
{
    const int lane = threadIdx.x & 31;
    int w        = (blockIdx.x * 256 + threadIdx.x) >> 5;
    const int nw = (gridDim.x * 256) >> 5;

    for (int e = w; e < E_; e += nw) {
        int src = __ldg(&ei[e]);
        int dst = __ldg(&ei[E_ + e]);
        float al = 0.f;
        if (lane < H_)
            al = g_score[(size_t)e * H_ + lane] / g_denom[(size_t)dst * H_ + lane];
        float a0 = __shfl_sync(0xffffffffu, al, lane >> 3);  // head of my group
        float a4 = __shfl_sync(0xffffffffu, al, 4);          // head 4

        const float4* xl4 = reinterpret_cast<const float4*>(g_xlr + (size_t)src * 320);
        float4*       ag4 = reinterpret_cast<float4*>(g_agg + (size_t)dst * 160);
        {
            float4 v = __ldg(xl4 + lane);
            asm volatile("red.global.add.v4.f32 [%0], {%1,%2,%3,%4};" ::
                         "l"(ag4 + lane),
                         "f"(a0 * v.x), "f"(a0 * v.y), "f"(a0 * v.z), "f"(a0 * v.w)
                         : "memory");
        }
        if (lane < 8) {
            float4 v = __ldg(xl4 + 32 + lane);
            asm volatile("red.global.add.v4.f32 [%0], {%1,%2,%3,%4};" ::
                         "l"(ag4 + 32 + lane),
                         "f"(a4 * v.x), "f"(a4 * v.y), "f"(a4 * v.z), "f"(a4 * v.w)
                         : "memory");
        }
    }
}

// ---------------------------------------------------------------------------
// LayerNorms (warp per row)
// ---------------------------------------------------------------------------
__global__ void ln1_k(const float* __restrict__ x, const float* __restrict__ bgat,
                      const float* __restrict__ g, const float* __restrict__ b)
{
    const int lane = threadIdx.x & 31;
    int row = (blockIdx.x * blockDim.x + threadIdx.x) >> 5;
    if (row >= N_) return;
    const float* xr = x     + (size_t)row * D_;
    const float* ar = g_agg + (size_t)row * D_;
    float v[H_];
    float s = 0.f, s2 = 0.f;
#pragma unroll
    for (int h = 0; h < H_; h++) {
        int c = h * 32 + lane;
        float t = xr[c] + ar[c] + __ldg(&bgat[c]);
        v[h] = t; s += t; s2 = fmaf(t, t, s2);
    }
#pragma unroll
    for (int o = 16; o > 0; o >>= 1) {
        s  += __shfl_xor_sync(0xffffffffu, s,  o);
        s2 += __shfl_xor_sync(0xffffffffu, s2, o);
    }
    float mean = s * (1.f / D_);
    float var  = s2 * (1.f / D_) - mean * mean;
    float inv  = rsqrtf(var + EPS_);
    float* op = g_out1 + (size_t)row * D_;
#pragma unroll
    for (int h = 0; h < H_; h++) {
        int c = h * 32 + lane;
        op[c] = (v[h] - mean) * inv * __ldg(&g[c]) + __ldg(&b[c]);
    }
}

__global__ void ln_hid_k(const float* __restrict__ g, const float* __restrict__ b)
{
    const int lane = threadIdx.x & 31;
    int row = (blockIdx.x * blockDim.x + threadIdx.x) >> 5;
    if (row >= N_) return;
    float* hp = g_hid + (size_t)row * HID_;
    float4 v[4];
    float s = 0.f, s2 = 0.f;
#pragma unroll
    for (int j = 0; j < 4; j++) {
        v[j] = *reinterpret_cast<const float4*>(hp + j * 128 + lane * 4);
        s += v[j].x + v[j].y + v[j].z + v[j].w;
        s2 = fmaf(v[j].x, v[j].x, fmaf(v[j].y, v[j].y,
             fmaf(v[j].z, v[j].z, fmaf(v[j].w, v[j].w, s2))));
    }
#pragma unroll
    for (int o = 16; o > 0; o >>= 1) {
        s  += __shfl_xor_sync(0xffffffffu, s,  o);
        s2 += __shfl_xor_sync(0xffffffffu, s2, o);
    }
    float mean = s * (1.f / HID_);
    float var  = s2 * (1.f / HID_) - mean * mean;
    float inv  = rsqrtf(var + EPS_);
#pragma unroll
    for (int j = 0; j < 4; j++) {
        int c = j * 128 + lane * 4;
        float4 gg = __ldg(reinterpret_cast<const float4*>(g + c));
        float4 bb = __ldg(reinterpret_cast<const float4*>(b + c));
        float4 o;
        o.x = (v[j].x - mean) * inv * gg.x + bb.x;
        o.y = (v[j].y - mean) * inv * gg.y + bb.y;
        o.z = (v[j].z - mean) * inv * gg.z + bb.z;
        o.w = (v[j].w - mean) * inv * gg.w + bb.w;
        *reinterpret_cast<float4*>(hp + c) = o;
    }
}

__global__ void ln2_k(const float* __restrict__ g, const float* __restrict__ b,
                      float* __restrict__ out)
{
    const int lane = threadIdx.x & 31;
    int row = (blockIdx.x * blockDim.x + threadIdx.x) >> 5;
    if (row >= N_) return;
    const float* r1 = g_out1 + (size_t)row * D_;
    const float* r2 = g_agg  + (size_t)row * D_;
    float v[H_];
    float s = 0.f, s2 = 0.f;
#pragma unroll
    for (int h = 0; h < H_; h++) {
        int c = h * 32 + lane;
        float t = r1[c] + r2[c];
        v[h] = t; s += t; s2 = fmaf(t, t, s2);
    }
#pragma unroll
    for (int o = 16; o > 0; o >>= 1) {
        s  += __shfl_xor_sync(0xffffffffu, s,  o);
        s2 += __shfl_xor_sync(0xffffffffu, s2, o);
    }
    float mean = s * (1.f / D_);
    float var  = s2 * (1.f / D_) - mean * mean;
    float inv  = rsqrtf(var + EPS_);
    float* op = out + (size_t)row * D_;
#pragma unroll
    for (int h = 0; h < H_; h++) {
        int c = h * 32 + lane;
        op[c] = (v[h] - mean) * inv * __ldg(&g[c]) + __ldg(&b[c]);
    }
}

// ---------------------------------------------------------------------------
// Launch
// ---------------------------------------------------------------------------
extern "C" void kernel_launch(void* const* d_in, const int* in_sizes, int n_in,
                              void* d_out, int out_size)
{
    const float* x     = (const float*)d_in[0];
    const int*   ei    = (const int*)  d_in[1];
    const float* eattr = (const float*)d_in[2];
    const float* Wl    = (const float*)d_in[5];
    const float* bl    = (const float*)d_in[6];
    const float* Wr    = (const float*)d_in[7];
    const float* br    = (const float*)d_in[8];
    const float* We    = (const float*)d_in[9];
    const float* att   = (const float*)d_in[10];
    const float* bgat  = (const float*)d_in[11];
    const float* g1    = (const float*)d_in[12];
    const float* b1    = (const float*)d_in[13];
    const float* Wm1   = (const float*)d_in[14];
    const float* bm1   = (const float*)d_in[15];
    const float* gm    = (const float*)d_in[16];
    const float* bm    = (const float*)d_in[17];
    const float* Wm2   = (const float*)d_in[18];
    const float* bm2   = (const float*)d_in[19];
    const float* g2    = (const float*)d_in[20];
    const float* b2    = (const float*)d_in[21];
    float* out = (float*)d_out;

    float *xlr, *Wcat, *bcat, *out1, *hid, *agg;
    cudaGetSymbolAddress((void**)&xlr,  g_xlr);
    cudaGetSymbolAddress((void**)&Wcat, g_Wcat);
    cudaGetSymbolAddress((void**)&bcat, g_bcat);
    cudaGetSymbolAddress((void**)&out1, g_out1);
    cudaGetSymbolAddress((void**)&hid,  g_hid);
    cudaGetSymbolAddress((void**)&agg,  g_agg);

    init_k<<<(N_ * D_ / 4 + 255) / 256, 256>>>();
    prep_w<<<(D_ * 320 + 255) / 256, 256>>>(Wl, bl, Wr, br);

    // xl|xr = x @ [Wl|Wr] + [bl|br]   -> g_xlr [N,320]
    sgemm_k<false><<<dim3(320 / 64, (N_ + 127) / 128), 256>>>(
        x, Wcat, bcat, xlr, N_, 320, D_);

    // GATv2 attention (edge_score: 1480 blocks -> 11840 warps = 5 * 2368)
    edge_score_k<<<1480, 256>>>(ei, eattr, We, att);
    edge_exp_k<<<(E_ + 255) / 256, 256>>>(ei);
    edge_agg_k<<<1184, 256>>>(ei);

    // out1 = LN(x + agg + b_gat)
    ln1_k<<<(N_ + 7) / 8, 256>>>(x, bgat, g1, b1);

    // hid = selu(out1 @ W_m1 + b_m1), then LN in place
    sgemm_k<true><<<dim3(HID_ / 64, (N_ + 127) / 128), 256>>>(
        out1, Wm1, bm1, hid, N_, HID_, D_);
    ln_hid_k<<<(N_ + 7) / 8, 256>>>(gm, bm);

    // mlp = hid @ W_m2 + b_m2  (reuse g_agg)
    sgemm_k<false><<<dim3((D_ + 63) / 64, (N_ + 127) / 128), 256>>>(
        hid, Wm2, bm2, agg, N_, D_, HID_);

    // out = LN(out1 + mlp)
    ln2_k<<<(N_ + 7) / 8, 256>>>(g2, b2, out);
}

// round 11
// speedup vs baseline: 1.9020x; 1.5446x over previous
#include <cuda_runtime.h>
#include <cstdint>
#include <cstddef>

// ---------------------------------------------------------------------------
// Problem constants
// ---------------------------------------------------------------------------
namespace {
constexpr int N_   = 50000;
constexpr int D_   = 160;     // = H*C
constexpr int H_   = 5;
constexpr int E_   = 800000;
constexpr int ED_  = 16;
constexpr int HID_ = 512;
constexpr float EPS_   = 1e-5f;
constexpr float SLOPE_ = 0.2f;
}

// ---------------------------------------------------------------------------
// Scratch buffers (device globals -- no allocation allowed)
// ---------------------------------------------------------------------------
__device__ float    g_xlr  [(size_t)N_ * 320];   // [N][320]: cols 0..159 = xl, 160..319 = xr
__device__ float    g_score[(size_t)E_ * H_];    // scores, then ex (in place)
__device__ unsigned g_mx   [N_ * H_];            // ordered-uint encoded segment max
__device__ float    g_denom[N_ * H_];
__device__ float    g_agg  [(size_t)N_ * D_];    // attention agg, later reused for MLP2 out
__device__ float    g_out1 [(size_t)N_ * D_];    // after first LN (residual for final LN)
__device__ float    g_hid  [(size_t)N_ * HID_];
__device__ float    g_Wcat [D_ * 320];           // [Wl | Wr]
__device__ float    g_bcat [320];

// ---------------------------------------------------------------------------
// Helpers
// ---------------------------------------------------------------------------
__device__ __forceinline__ unsigned fenc(float f) {
    unsigned u = __float_as_uint(f);
    return (u & 0x80000000u) ? ~u : (u | 0x80000000u);
}
__device__ __forceinline__ float fdec(unsigned u) {
    return (u & 0x80000000u) ? __uint_as_float(u & 0x7FFFFFFFu)
                             : __uint_as_float(~u);
}

__device__ __forceinline__ float selu_f(float x) {
    const float a = 1.6732632423543772f;
    const float s = 1.0507009873554805f;
    return x > 0.f ? s * x : s * a * (__expf(x) - 1.f);
}

// ---------------------------------------------------------------------------
// Init: zero agg + denom, fill mx with encoded -inf
// ---------------------------------------------------------------------------
__global__ void init_k() {
    int i = blockIdx.x * blockDim.x + threadIdx.x;
    if (i < N_ * D_ / 4)
        reinterpret_cast<float4*>(g_agg)[i] = make_float4(0.f, 0.f, 0.f, 0.f);
    if (i < N_ * H_) {
        g_denom[i] = 0.f;
        g_mx[i]    = 0x007FFFFFu;   // fenc(-inf)
    }
}

__global__ void prep_w(const float* __restrict__ Wl, const float* __restrict__ bl,
                       const float* __restrict__ Wr, const float* __restrict__ br) {
    int i = blockIdx.x * blockDim.x + threadIdx.x;
    if (i < D_ * 320) {
        int k = i / 320, c = i - k * 320;
        g_Wcat[i] = (c < D_) ? Wl[k * D_ + c] : Wr[k * D_ + (c - D_)];
    }
    if (i < 320)
        g_bcat[i] = (i < D_) ? bl[i] : br[i - D_];
}

// ---------------------------------------------------------------------------
// SGEMM (Round-7 proven version): C = A @ B + bias (+optional SELU)
// BM=128, BN=64, BK=32, 256 threads, 8x4 microtile, scalar FFMA.
// ---------------------------------------------------------------------------
template<bool DOSELU>
__global__ __launch_bounds__(256)
void sgemm_k(const float* __restrict__ A, const float* __restrict__ B,
             const float* __restrict__ bias, float* __restrict__ C,
             int M, int Nc, int K)
{
    constexpr int BM = 128, BN = 64, BK = 32, LDA = BM + 4;
    __shared__ float As[BK * LDA];
    __shared__ float Bs[BK * BN];

    const int tid = threadIdx.x;
    const int bm0 = blockIdx.y * BM;
    const int bn0 = blockIdx.x * BN;

    const int ra = tid >> 3;
    const int ka = (tid & 7) << 2;
    const int kb = tid >> 4;
    const int nb = (tid & 15) << 2;
    const int ty = tid >> 4;
    const int tx = tid & 15;

    float acc[8][4];
#pragma unroll
    for (int i = 0; i < 8; i++)
#pragma unroll
        for (int j = 0; j < 4; j++) acc[i][j] = 0.f;

    for (int k0 = 0; k0 < K; k0 += BK) {
#pragma unroll
        for (int r = 0; r < 4; r++) {
            int row = bm0 + ra + r * 32;
            float4 v = make_float4(0.f, 0.f, 0.f, 0.f);
            if (row < M)
                v = *reinterpret_cast<const float4*>(A + (size_t)row * K + k0 + ka);
            int sm = ra + r * 32;
            As[(ka + 0) * LDA + sm] = v.x;
            As[(ka + 1) * LDA + sm] = v.y;
            As[(ka + 2) * LDA + sm] = v.z;
            As[(ka + 3) * LDA + sm] = v.w;
        }
        {
            int colb = bn0 + nb;
#pragma unroll
            for (int r = 0; r < 2; r++) {
                int k = kb + r * 16;
                float4 v = make_float4(0.f, 0.f, 0.f, 0.f);
                if (colb < Nc)
                    v = *reinterpret_cast<const float4*>(B + (size_t)(k0 + k) * Nc + colb);
                *reinterpret_cast<float4*>(&Bs[k * BN + nb]) = v;
            }
        }
        __syncthreads();

#pragma unroll 8
        for (int kk = 0; kk < BK; kk++) {
            float4 a0 = *reinterpret_cast<const float4*>(&As[kk * LDA + ty * 4]);
            float4 a1 = *reinterpret_cast<const float4*>(&As[kk * LDA + 64 + ty * 4]);
            float4 b4 = *reinterpret_cast<const float4*>(&Bs[kk * BN + tx * 4]);
            float ar[8]  = {a0.x, a0.y, a0.z, a0.w, a1.x, a1.y, a1.z, a1.w};
            float brg[4] = {b4.x, b4.y, b4.z, b4.w};
#pragma unroll
            for (int i = 0; i < 8; i++)
#pragma unroll
                for (int j = 0; j < 4; j++)
                    acc[i][j] = fmaf(ar[i], brg[j], acc[i][j]);
        }
        __syncthreads();
    }

    int ncol = bn0 + tx * 4;
    if (ncol >= Nc) return;
    float4 bv = *reinterpret_cast<const float4*>(bias + ncol);
#pragma unroll
    for (int i = 0; i < 8; i++) {
        int row = bm0 + ((i < 4) ? (ty * 4 + i) : (64 + ty * 4 + (i - 4)));
        if (row < M) {
            float4 o = make_float4(acc[i][0] + bv.x, acc[i][1] + bv.y,
                                   acc[i][2] + bv.z, acc[i][3] + bv.w);
            if (DOSELU) {
                o.x = selu_f(o.x); o.y = selu_f(o.y);
                o.z = selu_f(o.z); o.w = selu_f(o.w);
            }
            *reinterpret_cast<float4*>(C + (size_t)row * Nc + ncol) = o;
        }
    }
}

// ---------------------------------------------------------------------------
// Edge pass 1 (v4): warp per TWO consecutive edges, all 5 heads per warp.
// We (80 regs/lane) + att (5) shared across both edges; acc/ea duplicated.
// 10 independent FMA chains + 10 interleaved butterflies + ~40 LDGs in
// flight per warp -> high per-warp ILP compensating the lower occupancy.
// __launch_bounds__(128, 3) caps regs at ~170 (12 warps/SM).
// ---------------------------------------------------------------------------
__global__ __launch_bounds__(128, 3)
void edge_score_k(const int* __restrict__ ei, const float* __restrict__ eattr,
                  const float* __restrict__ We, const float* __restrict__ att)
{
    const int lane = threadIdx.x & 31;
    const int w    = (blockIdx.x * 128 + threadIdx.x) >> 5;
    const int nw   = (gridDim.x * 128) >> 5;

    // hoist We / att into registers (coalesced, amortized over ~75 pairs)
    float we_r[H_][ED_];
    float att_r[H_];
#pragma unroll
    for (int h = 0; h < H_; h++) {
        att_r[h] = __ldg(&att[h * 32 + lane]);
#pragma unroll
        for (int k = 0; k < ED_; k++)
            we_r[h][k] = __ldg(&We[k * D_ + h * 32 + lane]);
    }

    for (int e = 2 * w; e < E_; e += 2 * nw) {
        // E_ is even and e is even, so e+1 < E_ always holds
        int src0 = __ldg(&ei[e]);
        int dst0 = __ldg(&ei[E_ + e]);
        int src1 = __ldg(&ei[e + 1]);
        int dst1 = __ldg(&ei[E_ + e + 1]);

        // edge features for BOTH edges: one contiguous 128B region
        const float4* ep = reinterpret_cast<const float4*>(eattr + (size_t)e * ED_);
        float4 ea[8];
#pragma unroll
        for (int q = 0; q < 8; q++) ea[q] = __ldg(ep + q);

        const float* xl0 = g_xlr + (size_t)src0 * 320;
        const float* xr0 = g_xlr + (size_t)dst0 * 320 + 160;
        const float* xl1 = g_xlr + (size_t)src1 * 320;
        const float* xr1 = g_xlr + (size_t)dst1 * 320 + 160;

        float acc0[H_], acc1[H_];
#pragma unroll
        for (int h = 0; h < H_; h++) {
            int col = h * 32 + lane;
            acc0[h] = xl0[col] + xr0[col];
            acc1[h] = xl1[col] + xr1[col];
        }

#pragma unroll
        for (int h = 0; h < H_; h++) {
            float a0 = acc0[h], a1 = acc1[h];
#pragma unroll
            for (int q = 0; q < 4; q++) {
                a0 = fmaf(ea[q].x,     we_r[h][4*q+0], a0);
                a0 = fmaf(ea[q].y,     we_r[h][4*q+1], a0);
                a0 = fmaf(ea[q].z,     we_r[h][4*q+2], a0);
                a0 = fmaf(ea[q].w,     we_r[h][4*q+3], a0);
                a1 = fmaf(ea[q + 4].x, we_r[h][4*q+0], a1);
                a1 = fmaf(ea[q + 4].y, we_r[h][4*q+1], a1);
                a1 = fmaf(ea[q + 4].z, we_r[h][4*q+2], a1);
                a1 = fmaf(ea[q + 4].w, we_r[h][4*q+3], a1);
            }
            acc0[h] = att_r[h] * (a0 > 0.f ? a0 : SLOPE_ * a0);
            acc1[h] = att_r[h] * (a1 > 0.f ? a1 : SLOPE_ * a1);
        }

        // xor-butterfly over lanes: 10 independent chains interleave
#pragma unroll
        for (int o = 16; o > 0; o >>= 1) {
#pragma unroll
            for (int h = 0; h < H_; h++) {
                acc0[h] += __shfl_xor_sync(0xffffffffu, acc0[h], o);
                acc1[h] += __shfl_xor_sync(0xffffffffu, acc1[h], o);
            }
        }

        // lanes 0..4 store edge e, lanes 8..12 store edge e+1
        if (lane < H_) {
            float v = acc0[0];
            if (lane == 1) v = acc0[1];
            else if (lane == 2) v = acc0[2];
            else if (lane == 3) v = acc0[3];
            else if (lane == 4) v = acc0[4];
            g_score[(size_t)e * H_ + lane] = v;
            atomicMax(&g_mx[(size_t)dst0 * H_ + lane], fenc(v));
        } else if (lane >= 8 && lane < 8 + H_) {
            int l8 = lane - 8;
            float v = acc1[0];
            if (l8 == 1) v = acc1[1];
            else if (l8 == 2) v = acc1[2];
            else if (l8 == 3) v = acc1[3];
            else if (l8 == 4) v = acc1[4];
            g_score[(size_t)(e + 1) * H_ + l8] = v;
            atomicMax(&g_mx[(size_t)dst1 * H_ + l8], fenc(v));
        }
    }
}

// ---------------------------------------------------------------------------
// Edge pass 2: one thread per edge -- single dst load, 5 exps, 5 atomics
// ---------------------------------------------------------------------------
__global__ void edge_exp_k(const int* __restrict__ ei)
{
    int e = blockIdx.x * blockDim.x + threadIdx.x;
    if (e >= E_) return;
    int dst = __ldg(&ei[E_ + e]);
    float*    sp  = g_score + (size_t)e * H_;
    unsigned* mxp = g_mx    + (size_t)dst * H_;
    float*    dp  = g_denom + (size_t)dst * H_;
#pragma unroll
    for (int h = 0; h < H_; h++) {
        float ex = __expf(sp[h] - fdec(mxp[h]));
        sp[h] = ex;
        atomicAdd(&dp[h], ex);
    }
}

// ---------------------------------------------------------------------------
// Edge pass 3: agg[dst] += alpha[e,h] * xl[src]  (vector f32x4 REDs)
// ---------------------------------------------------------------------------
__global__ __launch_bounds__(256)
void edge_agg_k(const int* __restrict__ ei)
{
    const int lane = threadIdx.x & 31;
    int w        = (blockIdx.x * 256 + threadIdx.x) >> 5;
    const int nw = (gridDim.x * 256) >> 5;

    for (int e = w; e < E_; e += nw) {
        int src = __ldg(&ei[e]);
        int dst = __ldg(&ei[E_ + e]);
        float al = 0.f;
        if (lane < H_)
            al = g_score[(size_t)e * H_ + lane] / g_denom[(size_t)dst * H_ + lane];
        float a0 = __shfl_sync(0xffffffffu, al, lane >> 3);  // head of my group
        float a4 = __shfl_sync(0xffffffffu, al, 4);          // head 4

        const float4* xl4 = reinterpret_cast<const float4*>(g_xlr + (size_t)src * 320);
        float4*       ag4 = reinterpret_cast<float4*>(g_agg + (size_t)dst * 160);
        {
            float4 v = __ldg(xl4 + lane);
            asm volatile("red.global.add.v4.f32 [%0], {%1,%2,%3,%4};" ::
                         "l"(ag4 + lane),
                         "f"(a0 * v.x), "f"(a0 * v.y), "f"(a0 * v.z), "f"(a0 * v.w)
                         : "memory");
        }
        if (lane < 8) {
            float4 v = __ldg(xl4 + 32 + lane);
            asm volatile("red.global.add.v4.f32 [%0], {%1,%2,%3,%4};" ::
                         "l"(ag4 + 32 + lane),
                         "f"(a4 * v.x), "f"(a4 * v.y), "f"(a4 * v.z), "f"(a4 * v.w)
                         : "memory");
        }
    }
}

// ---------------------------------------------------------------------------
// LayerNorms (warp per row)
// ---------------------------------------------------------------------------
__global__ void ln1_k(const float* __restrict__ x, const float* __restrict__ bgat,
                      const float* __restrict__ g, const float* __restrict__ b)
{
    const int lane = threadIdx.x & 31;
    int row = (blockIdx.x * blockDim.x + threadIdx.x) >> 5;
    if (row >= N_) return;
    const float* xr = x     + (size_t)row * D_;
    const float* ar = g_agg + (size_t)row * D_;
    float v[H_];
    float s = 0.f, s2 = 0.f;
#pragma unroll
    for (int h = 0; h < H_; h++) {
        int c = h * 32 + lane;
        float t = xr[c] + ar[c] + __ldg(&bgat[c]);
        v[h] = t; s += t; s2 = fmaf(t, t, s2);
    }
#pragma unroll
    for (int o = 16; o > 0; o >>= 1) {
        s  += __shfl_xor_sync(0xffffffffu, s,  o);
        s2 += __shfl_xor_sync(0xffffffffu, s2, o);
    }
    float mean = s * (1.f / D_);
    float var  = s2 * (1.f / D_) - mean * mean;
    float inv  = rsqrtf(var + EPS_);
    float* op = g_out1 + (size_t)row * D_;
#pragma unroll
    for (int h = 0; h < H_; h++) {
        int c = h * 32 + lane;
        op[c] = (v[h] - mean) * inv * __ldg(&g[c]) + __ldg(&b[c]);
    }
}

__global__ void ln_hid_k(const float* __restrict__ g, const float* __restrict__ b)
{
    const int lane = threadIdx.x & 31;
    int row = (blockIdx.x * blockDim.x + threadIdx.x) >> 5;
    if (row >= N_) return;
    float* hp = g_hid + (size_t)row * HID_;
    float4 v[4];
    float s = 0.f, s2 = 0.f;
#pragma unroll
    for (int j = 0; j < 4; j++) {
        v[j] = *reinterpret_cast<const float4*>(hp + j * 128 + lane * 4);
        s += v[j].x + v[j].y + v[j].z + v[j].w;
        s2 = fmaf(v[j].x, v[j].x, fmaf(v[j].y, v[j].y,
             fmaf(v[j].z, v[j].z, fmaf(v[j].w, v[j].w, s2))));
    }
#pragma unroll
    for (int o = 16; o > 0; o >>= 1) {
        s  += __shfl_xor_sync(0xffffffffu, s,  o);
        s2 += __shfl_xor_sync(0xffffffffu, s2, o);
    }
    float mean = s * (1.f / HID_);
    float var  = s2 * (1.f / HID_) - mean * mean;
    float inv  = rsqrtf(var + EPS_);
#pragma unroll
    for (int j = 0; j < 4; j++) {
        int c = j * 128 + lane * 4;
        float4 gg = __ldg(reinterpret_cast<const float4*>(g + c));
        float4 bb = __ldg(reinterpret_cast<const float4*>(b + c));
        float4 o;
        o.x = (v[j].x - mean) * inv * gg.x + bb.x;
        o.y = (v[j].y - mean) * inv * gg.y + bb.y;
        o.z = (v[j].z - mean) * inv * gg.z + bb.z;
        o.w = (v[j].w - mean) * inv * gg.w + bb.w;
        *reinterpret_cast<float4*>(hp + c) = o;
    }
}

__global__ void ln2_k(const float* __restrict__ g, const float* __restrict__ b,
                      float* __restrict__ out)
{
    const int lane = threadIdx.x & 31;
    int row = (blockIdx.x * blockDim.x + threadIdx.x) >> 5;
    if (row >= N_) return;
    const float* r1 = g_out1 + (size_t)row * D_;
    const float* r2 = g_agg  + (size_t)row * D_;
    float v[H_];
    float s = 0.f, s2 = 0.f;
#pragma unroll
    for (int h = 0; h < H_; h++) {
        int c = h * 32 + lane;
        float t = r1[c] + r2[c];
        v[h] = t; s += t; s2 = fmaf(t, t, s2);
    }
#pragma unroll
    for (int o = 16; o > 0; o >>= 1) {
        s  += __shfl_xor_sync(0xffffffffu, s,  o);
        s2 += __shfl_xor_sync(0xffffffffu, s2, o);
    }
    float mean = s * (1.f / D_);
    float var  = s2 * (1.f / D_) - mean * mean;
    float inv  = rsqrtf(var + EPS_);
    float* op = out + (size_t)row * D_;
#pragma unroll
    for (int h = 0; h < H_; h++) {
        int c = h * 32 + lane;
        op[c] = (v[h] - mean) * inv * __ldg(&g[c]) + __ldg(&b[c]);
    }
}

// ---------------------------------------------------------------------------
// Launch
// ---------------------------------------------------------------------------
extern "C" void kernel_launch(void* const* d_in, const int* in_sizes, int n_in,
                              void* d_out, int out_size)
{
    const float* x     = (const float*)d_in[0];
    const int*   ei    = (const int*)  d_in[1];
    const float* eattr = (const float*)d_in[2];
    const float* Wl    = (const float*)d_in[5];
    const float* bl    = (const float*)d_in[6];
    const float* Wr    = (const float*)d_in[7];
    const float* br    = (const float*)d_in[8];
    const float* We    = (const float*)d_in[9];
    const float* att   = (const float*)d_in[10];
    const float* bgat  = (const float*)d_in[11];
    const float* g1    = (const float*)d_in[12];
    const float* b1    = (const float*)d_in[13];
    const float* Wm1   = (const float*)d_in[14];
    const float* bm1   = (const float*)d_in[15];
    const float* gm    = (const float*)d_in[16];
    const float* bm    = (const float*)d_in[17];
    const float* Wm2   = (const float*)d_in[18];
    const float* bm2   = (const float*)d_in[19];
    const float* g2    = (const float*)d_in[20];
    const float* b2    = (const float*)d_in[21];
    float* out = (float*)d_out;

    float *xlr, *Wcat, *bcat, *out1, *hid, *agg;
    cudaGetSymbolAddress((void**)&xlr,  g_xlr);
    cudaGetSymbolAddress((void**)&Wcat, g_Wcat);
    cudaGetSymbolAddress((void**)&bcat, g_bcat);
    cudaGetSymbolAddress((void**)&out1, g_out1);
    cudaGetSymbolAddress((void**)&hid,  g_hid);
    cudaGetSymbolAddress((void**)&agg,  g_agg);

    init_k<<<(N_ * D_ / 4 + 255) / 256, 256>>>();
    prep_w<<<(D_ * 320 + 255) / 256, 256>>>(Wl, bl, Wr, br);

    // xl|xr = x @ [Wl|Wr] + [bl|br]   -> g_xlr [N,320]
    sgemm_k<false><<<dim3(320 / 64, (N_ + 127) / 128), 256>>>(
        x, Wcat, bcat, xlr, N_, 320, D_);

    // GATv2 attention (edge_score: 1332 blocks x 128 thr = 5328 warps,
    // each handling ~75 edge PAIRS)
    edge_score_k<<<1332, 128>>>(ei, eattr, We, att);
    edge_exp_k<<<(E_ + 255) / 256, 256>>>(ei);
    edge_agg_k<<<1184, 256>>>(ei);

    // out1 = LN(x + agg + b_gat)
    ln1_k<<<(N_ + 7) / 8, 256>>>(x, bgat, g1, b1);

    // hid = selu(out1 @ W_m1 + b_m1), then LN in place
    sgemm_k<true><<<dim3(HID_ / 64, (N_ + 127) / 128), 256>>>(
        out1, Wm1, bm1, hid, N_, HID_, D_);
    ln_hid_k<<<(N_ + 7) / 8, 256>>>(gm, bm);

    // mlp = hid @ W_m2 + b_m2  (reuse g_agg)
    sgemm_k<false><<<dim3((D_ + 63) / 64, (N_ + 127) / 128), 256>>>(
        hid, Wm2, bm2, agg, N_, D_, HID_);

    // out = LN(out1 + mlp)
    ln2_k<<<(N_ + 7) / 8, 256>>>(g2, b2, out);
}

// round 14
// speedup vs baseline: 2.3297x; 1.2248x over previous
#include <cuda_runtime.h>
#include <cstdint>
#include <cstddef>

// ---------------------------------------------------------------------------
// Problem constants
// ---------------------------------------------------------------------------
namespace {
constexpr int N_   = 50000;
constexpr int D_   = 160;     // = H*C
constexpr int H_   = 5;
constexpr int E_   = 800000;
constexpr int ED_  = 16;
constexpr int HID_ = 512;
constexpr float EPS_   = 1e-5f;
constexpr float SLOPE_ = 0.2f;
}

// ---------------------------------------------------------------------------
// Scratch buffers (device globals -- no allocation allowed)
// ---------------------------------------------------------------------------
__device__ float    g_xlr  [(size_t)N_ * 320];   // [N][320]: cols 0..159 = xl, 160..319 = xr
__device__ float    g_score[(size_t)E_ * H_];    // scores, then ex (in place)
__device__ unsigned g_mx   [N_ * H_];            // ordered-uint encoded segment max
__device__ float    g_denom[N_ * H_];
__device__ float    g_agg  [(size_t)N_ * D_];    // attention agg, later reused for MLP2 out
__device__ float    g_out1 [(size_t)N_ * D_];    // after first LN (residual for final LN)
__device__ float    g_hid  [(size_t)N_ * HID_];
__device__ float    g_Wcat [D_ * 320];           // [Wl | Wr]
__device__ float    g_bcat [320];

// ---------------------------------------------------------------------------
// Helpers
// ---------------------------------------------------------------------------
__device__ __forceinline__ unsigned fenc(float f) {
    unsigned u = __float_as_uint(f);
    return (u & 0x80000000u) ? ~u : (u | 0x80000000u);
}
__device__ __forceinline__ float fdec(unsigned u) {
    return (u & 0x80000000u) ? __uint_as_float(u & 0x7FFFFFFFu)
                             : __uint_as_float(~u);
}

__device__ __forceinline__ float selu_f(float x) {
    const float a = 1.6732632423543772f;
    const float s = 1.0507009873554805f;
    return x > 0.f ? s * x : s * a * (__expf(x) - 1.f);
}

// round fp32 -> tf32 (result as fp32 bit pattern with low mantissa bits zeroed)
__device__ __forceinline__ float tf32f(float x) {
    unsigned u;
    asm("cvt.rna.tf32.f32 %0, %1;" : "=r"(u) : "f"(x));
    return __uint_as_float(u);
}

// ---------------------------------------------------------------------------
// Init: zero agg + denom, fill mx with encoded -inf
// ---------------------------------------------------------------------------
__global__ void init_k() {
    int i = blockIdx.x * blockDim.x + threadIdx.x;
    if (i < N_ * D_ / 4)
        reinterpret_cast<float4*>(g_agg)[i] = make_float4(0.f, 0.f, 0.f, 0.f);
    if (i < N_ * H_) {
        g_denom[i] = 0.f;
        g_mx[i]    = 0x007FFFFFu;   // fenc(-inf)
    }
}

__global__ void prep_w(const float* __restrict__ Wl, const float* __restrict__ bl,
                       const float* __restrict__ Wr, const float* __restrict__ br) {
    int i = blockIdx.x * blockDim.x + threadIdx.x;
    if (i < D_ * 320) {
        int k = i / 320, c = i - k * 320;
        g_Wcat[i] = (c < D_) ? Wl[k * D_ + c] : Wr[k * D_ + (c - D_)];
    }
    if (i < 320)
        g_bcat[i] = (i < D_) ? bl[i] : br[i - D_];
}

// ---------------------------------------------------------------------------
// TF32 tensor-core GEMM: C[M,Nc] = A[M,K] @ B[K,Nc] + bias (+optional SELU)
// mma.sync.aligned.m16n8k8.row.col.f32.tf32.tf32.f32
// BM=128, BN=64, BK=32; 256 threads = 8 warps (4 along M x 2 along N);
// each warp computes a 32x32 tile = 2 m16-tiles x 4 n8-tiles.
// FIX vs R13: epilogue column guard restored (col < Nc on bias load + store).
// ---------------------------------------------------------------------------
template<bool DOSELU>
__global__ __launch_bounds__(256)
void tgemm_k(const float* __restrict__ A, const float* __restrict__ B,
             const float* __restrict__ bias, float* __restrict__ C,
             int M, int Nc, int K)
{
    constexpr int BM = 128, BN = 64, BK = 32, LDA = 136, LDB = 72;
    __shared__ float As[BK * LDA];   // As[k][m]
    __shared__ float Bs[BK * LDB];   // Bs[k][n]

    const int tid  = threadIdx.x;
    const int bm0  = blockIdx.y * BM;
    const int bn0  = blockIdx.x * BN;
    const int warp = tid >> 5;
    const int lane = tid & 31;
    const int g    = lane >> 2;       // groupID 0..7
    const int tig  = lane & 3;        // thread-in-group 0..3
    const int wm   = (warp & 3) * 32; // warp M offset
    const int wn   = (warp >> 2) * 32;// warp N offset

    const int ra = tid >> 3;          // A-stage row 0..31
    const int ka = (tid & 7) << 2;    // A-stage k 0,4,...,28
    const int kb = tid >> 4;          // B-stage k 0..15
    const int nb = (tid & 15) << 2;   // B-stage n 0..60

    float acc[2][4][4];
#pragma unroll
    for (int mt = 0; mt < 2; mt++)
#pragma unroll
        for (int nt = 0; nt < 4; nt++)
#pragma unroll
            for (int r = 0; r < 4; r++) acc[mt][nt][r] = 0.f;

    for (int k0 = 0; k0 < K; k0 += BK) {
        // --- stage A tile (transpose + tf32 round)
#pragma unroll
        for (int r = 0; r < 4; r++) {
            int row = bm0 + ra + r * 32;
            float4 v = make_float4(0.f, 0.f, 0.f, 0.f);
            if (row < M)
                v = *reinterpret_cast<const float4*>(A + (size_t)row * K + k0 + ka);
            int sm = ra + r * 32;
            As[(ka + 0) * LDA + sm] = tf32f(v.x);
            As[(ka + 1) * LDA + sm] = tf32f(v.y);
            As[(ka + 2) * LDA + sm] = tf32f(v.z);
            As[(ka + 3) * LDA + sm] = tf32f(v.w);
        }
        // --- stage B tile (tf32 round)
        {
            int colb = bn0 + nb;
#pragma unroll
            for (int r = 0; r < 2; r++) {
                int k = kb + r * 16;
                float4 v = make_float4(0.f, 0.f, 0.f, 0.f);
                if (colb < Nc)
                    v = *reinterpret_cast<const float4*>(B + (size_t)(k0 + k) * Nc + colb);
                Bs[k * LDB + nb + 0] = tf32f(v.x);
                Bs[k * LDB + nb + 1] = tf32f(v.y);
                Bs[k * LDB + nb + 2] = tf32f(v.z);
                Bs[k * LDB + nb + 3] = tf32f(v.w);
            }
        }
        __syncthreads();

#pragma unroll
        for (int kk = 0; kk < BK; kk += 8) {
            unsigned a[2][4];
#pragma unroll
            for (int mt = 0; mt < 2; mt++) {
                int m0 = wm + mt * 16;
                a[mt][0] = __float_as_uint(As[(kk + tig)     * LDA + m0 + g]);
                a[mt][1] = __float_as_uint(As[(kk + tig)     * LDA + m0 + g + 8]);
                a[mt][2] = __float_as_uint(As[(kk + tig + 4) * LDA + m0 + g]);
                a[mt][3] = __float_as_uint(As[(kk + tig + 4) * LDA + m0 + g + 8]);
            }
            unsigned b[4][2];
#pragma unroll
            for (int nt = 0; nt < 4; nt++) {
                int n0 = wn + nt * 8;
                b[nt][0] = __float_as_uint(Bs[(kk + tig)     * LDB + n0 + g]);
                b[nt][1] = __float_as_uint(Bs[(kk + tig + 4) * LDB + n0 + g]);
            }
#pragma unroll
            for (int mt = 0; mt < 2; mt++)
#pragma unroll
                for (int nt = 0; nt < 4; nt++) {
                    asm volatile(
                        "mma.sync.aligned.m16n8k8.row.col.f32.tf32.tf32.f32 "
                        "{%0,%1,%2,%3}, {%4,%5,%6,%7}, {%8,%9}, {%0,%1,%2,%3};"
                        : "+f"(acc[mt][nt][0]), "+f"(acc[mt][nt][1]),
                          "+f"(acc[mt][nt][2]), "+f"(acc[mt][nt][3])
                        : "r"(a[mt][0]), "r"(a[mt][1]), "r"(a[mt][2]), "r"(a[mt][3]),
                          "r"(b[nt][0]), "r"(b[nt][1]));
                }
        }
        __syncthreads();
    }

    // --- epilogue: +bias (+SELU), float2 stores, GUARDED on row AND column
#pragma unroll
    for (int mt = 0; mt < 2; mt++) {
        int row0 = bm0 + wm + mt * 16 + g;
#pragma unroll
        for (int nt = 0; nt < 4; nt++) {
            int col = bn0 + wn + nt * 8 + 2 * tig;
            if (col >= Nc) continue;          // col even, Nc even -> pair safe
            float2 bv = *reinterpret_cast<const float2*>(bias + col);
            if (row0 < M) {
                float2 o = make_float2(acc[mt][nt][0] + bv.x, acc[mt][nt][1] + bv.y);
                if (DOSELU) { o.x = selu_f(o.x); o.y = selu_f(o.y); }
                *reinterpret_cast<float2*>(C + (size_t)row0 * Nc + col) = o;
            }
            if (row0 + 8 < M) {
                float2 o = make_float2(acc[mt][nt][2] + bv.x, acc[mt][nt][3] + bv.y);
                if (DOSELU) { o.x = selu_f(o.x); o.y = selu_f(o.y); }
                *reinterpret_cast<float2*>(C + (size_t)(row0 + 8) * Nc + col) = o;
            }
        }
    }
}

// ---------------------------------------------------------------------------
// Edge pass 1 (R11 version, unchanged): warp per TWO consecutive edges.
// ---------------------------------------------------------------------------
__global__ __launch_bounds__(128, 3)
void edge_score_k(const int* __restrict__ ei, const float* __restrict__ eattr,
                  const float* __restrict__ We, const float* __restrict__ att)
{
    const int lane = threadIdx.x & 31;
    const int w    = (blockIdx.x * 128 + threadIdx.x) >> 5;
    const int nw   = (gridDim.x * 128) >> 5;

    float we_r[H_][ED_];
    float att_r[H_];
#pragma unroll
    for (int h = 0; h < H_; h++) {
        att_r[h] = __ldg(&att[h * 32 + lane]);
#pragma unroll
        for (int k = 0; k < ED_; k++)
            we_r[h][k] = __ldg(&We[k * D_ + h * 32 + lane]);
    }

    for (int e = 2 * w; e < E_; e += 2 * nw) {
        int src0 = __ldg(&ei[e]);
        int dst0 = __ldg(&ei[E_ + e]);
        int src1 = __ldg(&ei[e + 1]);
        int dst1 = __ldg(&ei[E_ + e + 1]);

        const float4* ep = reinterpret_cast<const float4*>(eattr + (size_t)e * ED_);
        float4 ea[8];
#pragma unroll
        for (int q = 0; q < 8; q++) ea[q] = __ldg(ep + q);

        const float* xl0 = g_xlr + (size_t)src0 * 320;
        const float* xr0 = g_xlr + (size_t)dst0 * 320 + 160;
        const float* xl1 = g_xlr + (size_t)src1 * 320;
        const float* xr1 = g_xlr + (size_t)dst1 * 320 + 160;

        float acc0[H_], acc1[H_];
#pragma unroll
        for (int h = 0; h < H_; h++) {
            int col = h * 32 + lane;
            acc0[h] = xl0[col] + xr0[col];
            acc1[h] = xl1[col] + xr1[col];
        }

#pragma unroll
        for (int h = 0; h < H_; h++) {
            float a0 = acc0[h], a1 = acc1[h];
#pragma unroll
            for (int q = 0; q < 4; q++) {
                a0 = fmaf(ea[q].x,     we_r[h][4*q+0], a0);
                a0 = fmaf(ea[q].y,     we_r[h][4*q+1], a0);
                a0 = fmaf(ea[q].z,     we_r[h][4*q+2], a0);
                a0 = fmaf(ea[q].w,     we_r[h][4*q+3], a0);
                a1 = fmaf(ea[q + 4].x, we_r[h][4*q+0], a1);
                a1 = fmaf(ea[q + 4].y, we_r[h][4*q+1], a1);
                a1 = fmaf(ea[q + 4].z, we_r[h][4*q+2], a1);
                a1 = fmaf(ea[q + 4].w, we_r[h][4*q+3], a1);
            }
            acc0[h] = att_r[h] * (a0 > 0.f ? a0 : SLOPE_ * a0);
            acc1[h] = att_r[h] * (a1 > 0.f ? a1 : SLOPE_ * a1);
        }

#pragma unroll
        for (int o = 16; o > 0; o >>= 1) {
#pragma unroll
            for (int h = 0; h < H_; h++) {
                acc0[h] += __shfl_xor_sync(0xffffffffu, acc0[h], o);
                acc1[h] += __shfl_xor_sync(0xffffffffu, acc1[h], o);
            }
        }

        if (lane < H_) {
            float v = acc0[0];
            if (lane == 1) v = acc0[1];
            else if (lane == 2) v = acc0[2];
            else if (lane == 3) v = acc0[3];
            else if (lane == 4) v = acc0[4];
            g_score[(size_t)e * H_ + lane] = v;
            atomicMax(&g_mx[(size_t)dst0 * H_ + lane], fenc(v));
        } else if (lane >= 8 && lane < 8 + H_) {
            int l8 = lane - 8;
            float v = acc1[0];
            if (l8 == 1) v = acc1[1];
            else if (l8 == 2) v = acc1[2];
            else if (l8 == 3) v = acc1[3];
            else if (l8 == 4) v = acc1[4];
            g_score[(size_t)(e + 1) * H_ + l8] = v;
            atomicMax(&g_mx[(size_t)dst1 * H_ + l8], fenc(v));
        }
    }
}

// ---------------------------------------------------------------------------
// Edge pass 2: one thread per edge
// ---------------------------------------------------------------------------
__global__ void edge_exp_k(const int* __restrict__ ei)
{
    int e = blockIdx.x * blockDim.x + threadIdx.x;
    if (e >= E_) return;
    int dst = __ldg(&ei[E_ + e]);
    float*    sp  = g_score + (size_t)e * H_;
    unsigned* mxp = g_mx    + (size_t)dst * H_;
    float*    dp  = g_denom + (size_t)dst * H_;
#pragma unroll
    for (int h = 0; h < H_; h++) {
        float ex = __expf(sp[h] - fdec(mxp[h]));
        sp[h] = ex;
        atomicAdd(&dp[h], ex);
    }
}

// ---------------------------------------------------------------------------
// Edge pass 3: agg[dst] += alpha[e,h] * xl[src]  (vector f32x4 REDs)
// ---------------------------------------------------------------------------
__global__ __launch_bounds__(256)
void edge_agg_k(const int* __restrict__ ei)
{
    const int lane = threadIdx.x & 31;
    int w        = (blockIdx.x * 256 + threadIdx.x) >> 5;
    const int nw = (gridDim.x * 256) >> 5;

    for (int e = w; e < E_; e += nw) {
        int src = __ldg(&ei[e]);
        int dst = __ldg(&ei[E_ + e]);
        float al = 0.f;
        if (lane < H_)
            al = g_score[(size_t)e * H_ + lane] / g_denom[(size_t)dst * H_ + lane];
        float a0 = __shfl_sync(0xffffffffu, al, lane >> 3);
        float a4 = __shfl_sync(0xffffffffu, al, 4);

        const float4* xl4 = reinterpret_cast<const float4*>(g_xlr + (size_t)src * 320);
        float4*       ag4 = reinterpret_cast<float4*>(g_agg + (size_t)dst * 160);
        {
            float4 v = __ldg(xl4 + lane);
            asm volatile("red.global.add.v4.f32 [%0], {%1,%2,%3,%4};" ::
                         "l"(ag4 + lane),
                         "f"(a0 * v.x), "f"(a0 * v.y), "f"(a0 * v.z), "f"(a0 * v.w)
                         : "memory");
        }
        if (lane < 8) {
            float4 v = __ldg(xl4 + 32 + lane);
            asm volatile("red.global.add.v4.f32 [%0], {%1,%2,%3,%4};" ::
                         "l"(ag4 + 32 + lane),
                         "f"(a4 * v.x), "f"(a4 * v.y), "f"(a4 * v.z), "f"(a4 * v.w)
                         : "memory");
        }
    }
}

// ---------------------------------------------------------------------------
// LayerNorms (warp per row)
// ---------------------------------------------------------------------------
__global__ void ln1_k(const float* __restrict__ x, const float* __restrict__ bgat,
                      const float* __restrict__ g, const float* __restrict__ b)
{
    const int lane = threadIdx.x & 31;
    int row = (blockIdx.x * blockDim.x + threadIdx.x) >> 5;
    if (row >= N_) return;
    const float* xr = x     + (size_t)row * D_;
    const float* ar = g_agg + (size_t)row * D_;
    float v[H_];
    float s = 0.f, s2 = 0.f;
#pragma unroll
    for (int h = 0; h < H_; h++) {
        int c = h * 32 + lane;
        float t = xr[c] + ar[c] + __ldg(&bgat[c]);
        v[h] = t; s += t; s2 = fmaf(t, t, s2);
    }
#pragma unroll
    for (int o = 16; o > 0; o >>= 1) {
        s  += __shfl_xor_sync(0xffffffffu, s,  o);
        s2 += __shfl_xor_sync(0xffffffffu, s2, o);
    }
    float mean = s * (1.f / D_);
    float var  = s2 * (1.f / D_) - mean * mean;
    float inv  = rsqrtf(var + EPS_);
    float* op = g_out1 + (size_t)row * D_;
#pragma unroll
    for (int h = 0; h < H_; h++) {
        int c = h * 32 + lane;
        op[c] = (v[h] - mean) * inv * __ldg(&g[c]) + __ldg(&b[c]);
    }
}

__global__ void ln_hid_k(const float* __restrict__ g, const float* __restrict__ b)
{
    const int lane = threadIdx.x & 31;
    int row = (blockIdx.x * blockDim.x + threadIdx.x) >> 5;
    if (row >= N_) return;
    float* hp = g_hid + (size_t)row * HID_;
    float4 v[4];
    float s = 0.f, s2 = 0.f;
#pragma unroll
    for (int j = 0; j < 4; j++) {
        v[j] = *reinterpret_cast<const float4*>(hp + j * 128 + lane * 4);
        s += v[j].x + v[j].y + v[j].z + v[j].w;
        s2 = fmaf(v[j].x, v[j].x, fmaf(v[j].y, v[j].y,
             fmaf(v[j].z, v[j].z, fmaf(v[j].w, v[j].w, s2))));
    }
#pragma unroll
    for (int o = 16; o > 0; o >>= 1) {
        s  += __shfl_xor_sync(0xffffffffu, s,  o);
        s2 += __shfl_xor_sync(0xffffffffu, s2, o);
    }
    float mean = s * (1.f / HID_);
    float var  = s2 * (1.f / HID_) - mean * mean;
    float inv  = rsqrtf(var + EPS_);
#pragma unroll
    for (int j = 0; j < 4; j++) {
        int c = j * 128 + lane * 4;
        float4 gg = __ldg(reinterpret_cast<const float4*>(g + c));
        float4 bb = __ldg(reinterpret_cast<const float4*>(b + c));
        float4 o;
        o.x = (v[j].x - mean) * inv * gg.x + bb.x;
        o.y = (v[j].y - mean) * inv * gg.y + bb.y;
        o.z = (v[j].z - mean) * inv * gg.z + bb.z;
        o.w = (v[j].w - mean) * inv * gg.w + bb.w;
        *reinterpret_cast<float4*>(hp + c) = o;
    }
}

__global__ void ln2_k(const float* __restrict__ g, const float* __restrict__ b,
                      float* __restrict__ out)
{
    const int lane = threadIdx.x & 31;
    int row = (blockIdx.x * blockDim.x + threadIdx.x) >> 5;
    if (row >= N_) return;
    const float* r1 = g_out1 + (size_t)row * D_;
    const float* r2 = g_agg  + (size_t)row * D_;
    float v[H_];
    float s = 0.f, s2 = 0.f;
#pragma unroll
    for (int h = 0; h < H_; h++) {
        int c = h * 32 + lane;
        float t = r1[c] + r2[c];
        v[h] = t; s += t; s2 = fmaf(t, t, s2);
    }
#pragma unroll
    for (int o = 16; o > 0; o >>= 1) {
        s  += __shfl_xor_sync(0xffffffffu, s,  o);
        s2 += __shfl_xor_sync(0xffffffffu, s2, o);
    }
    float mean = s * (1.f / D_);
    float var  = s2 * (1.f / D_) - mean * mean;
    float inv  = rsqrtf(var + EPS_);
    float* op = out + (size_t)row * D_;
#pragma unroll
    for (int h = 0; h < H_; h++) {
        int c = h * 32 + lane;
        op[c] = (v[h] - mean) * inv * __ldg(&g[c]) + __ldg(&b[c]);
    }
}

// ---------------------------------------------------------------------------
// Launch
// ---------------------------------------------------------------------------
extern "C" void kernel_launch(void* const* d_in, const int* in_sizes, int n_in,
                              void* d_out, int out_size)
{
    const float* x     = (const float*)d_in[0];
    const int*   ei    = (const int*)  d_in[1];
    const float* eattr = (const float*)d_in[2];
    const float* Wl    = (const float*)d_in[5];
    const float* bl    = (const float*)d_in[6];
    const float* Wr    = (const float*)d_in[7];
    const float* br    = (const float*)d_in[8];
    const float* We    = (const float*)d_in[9];
    const float* att   = (const float*)d_in[10];
    const float* bgat  = (const float*)d_in[11];
    const float* g1    = (const float*)d_in[12];
    const float* b1    = (const float*)d_in[13];
    const float* Wm1   = (const float*)d_in[14];
    const float* bm1   = (const float*)d_in[15];
    const float* gm    = (const float*)d_in[16];
    const float* bm    = (const float*)d_in[17];
    const float* Wm2   = (const float*)d_in[18];
    const float* bm2   = (const float*)d_in[19];
    const float* g2    = (const float*)d_in[20];
    const float* b2    = (const float*)d_in[21];
    float* out = (float*)d_out;

    float *xlr, *Wcat, *bcat, *out1, *hid, *agg;
    cudaGetSymbolAddress((void**)&xlr,  g_xlr);
    cudaGetSymbolAddress((void**)&Wcat, g_Wcat);
    cudaGetSymbolAddress((void**)&bcat, g_bcat);
    cudaGetSymbolAddress((void**)&out1, g_out1);
    cudaGetSymbolAddress((void**)&hid,  g_hid);
    cudaGetSymbolAddress((void**)&agg,  g_agg);

    init_k<<<(N_ * D_ / 4 + 255) / 256, 256>>>();
    prep_w<<<(D_ * 320 + 255) / 256, 256>>>(Wl, bl, Wr, br);

    // xl|xr = x @ [Wl|Wr] + [bl|br]   -> g_xlr [N,320]
    tgemm_k<false><<<dim3(320 / 64, (N_ + 127) / 128), 256>>>(
        x, Wcat, bcat, xlr, N_, 320, D_);

    // GATv2 attention
    edge_score_k<<<1332, 128>>>(ei, eattr, We, att);
    edge_exp_k<<<(E_ + 255) / 256, 256>>>(ei);
    edge_agg_k<<<1184, 256>>>(ei);

    // out1 = LN(x + agg + b_gat)
    ln1_k<<<(N_ + 7) / 8, 256>>>(x, bgat, g1, b1);

    // hid = selu(out1 @ W_m1 + b_m1), then LN in place
    tgemm_k<true><<<dim3(HID_ / 64, (N_ + 127) / 128), 256>>>(
        out1, Wm1, bm1, hid, N_, HID_, D_);
    ln_hid_k<<<(N_ + 7) / 8, 256>>>(gm, bm);

    // mlp = hid @ W_m2 + b_m2  (reuse g_agg)
    tgemm_k<false><<<dim3((D_ + 63) / 64, (N_ + 127) / 128), 256>>>(
        hid, Wm2, bm2, agg, N_, D_, HID_);

    // out = LN(out1 + mlp)
    ln2_k<<<(N_ + 7) / 8, 256>>>(g2, b2, out);
}